// round 5
// baseline (speedup 1.0000x reference)
#include <cuda_runtime.h>
#include <cstdint>

#define N_NODES 100000
#define IN_DIM  128
#define EMB     64
#define NCLS    18
#define MAX_E   3200000

// ---------------- scratch (static device globals; no allocs) ----------------
__device__ int   g_cnt [N_NODES];     // in-degree (excl self loop)
__device__ int   g_rowp[N_NODES];     // CSR row start
__device__ int   g_cur [N_NODES];     // fill cursor
__device__ float g_dis [N_NODES];     // rsqrt(deg incl self loop)
__device__ float g_h1  [N_NODES * EMB];
__device__ float g_r1  [N_NODES * EMB];   // relu(agg1 + b1)
__device__ float g_h2  [N_NODES * NCLS];
__device__ int2  g_csr [MAX_E];       // (src, bitcast norm), dst-sorted

// ---------------- kernels ---------------------------------------------------

__global__ void k_zero() {
    int i = blockIdx.x * blockDim.x + threadIdx.x;
    if (i < N_NODES) g_cnt[i] = 0;
}

// in-degree count (edge_index is int32 per harness dtype rules)
__global__ void k_deg(const int* __restrict__ ei, int E) {
    int e = blockIdx.x * blockDim.x + threadIdx.x;
    if (e < E) {
        int d = __ldg(ei + E + e);
        if ((unsigned)d < N_NODES) atomicAdd(&g_cnt[d], 1);
    }
}

// single-block exclusive scan over g_cnt -> g_rowp/g_cur; also g_dis
__global__ void k_scan() {
    __shared__ int ssum[1024];
    const int CH = (N_NODES + 1023) / 1024;   // 98
    int t  = threadIdx.x;
    int lo = t * CH;
    int hi = min(lo + CH, N_NODES);
    int s = 0;
    for (int i = lo; i < hi; ++i) s += g_cnt[i];
    ssum[t] = s;
    __syncthreads();
    for (int off = 1; off < 1024; off <<= 1) {
        int u = (t >= off) ? ssum[t - off] : 0;
        __syncthreads();
        ssum[t] += u;
        __syncthreads();
    }
    int run = ssum[t] - s;   // exclusive base for this thread's chunk
    for (int i = lo; i < hi; ++i) {
        int c = g_cnt[i];
        g_rowp[i] = run;
        g_cur [i] = run;
        g_dis [i] = rsqrtf((float)(c + 1));
        run += c;
    }
}

// scatter (src, norm) into dst-sorted CSR slots
__global__ void k_fill(const int* __restrict__ ei, int E) {
    int e = blockIdx.x * blockDim.x + threadIdx.x;
    if (e >= E) return;
    int s = __ldg(ei + e);
    int d = __ldg(ei + E + e);
    if ((unsigned)s >= N_NODES) s = 0;
    if ((unsigned)d >= N_NODES) d = 0;
    float nrm = g_dis[s] * g_dis[d];
    int pos = atomicAdd(&g_cur[d], 1);
    g_csr[pos] = make_int2(s, __float_as_int(nrm));
}

// h1 = x @ W1  (100000x128 @ 128x64). W1 transposed in smem for LDS.128;
// each thread owns one output column and processes 2 rows per iteration,
// reusing the weight vector (8 FMA per LDS.128).
#define G1_ROWS 64
__global__ void k_gemm1(const float* __restrict__ x, const float* __restrict__ W1) {
    __shared__ float sWt[EMB * IN_DIM];  // sWt[c*128 + k], 32 KB
    for (int i = threadIdx.x; i < IN_DIM * EMB; i += blockDim.x) {
        int k = i >> 6, c = i & 63;      // W1 is [128,64] row-major
        sWt[c * IN_DIM + k] = W1[i];
    }
    __syncthreads();
    int col  = threadIdx.x;                   // 0..63
    int row0 = blockIdx.x * G1_ROWS;
    const float4* wv = (const float4*)&sWt[col * IN_DIM];
    for (int r = 0; r < G1_ROWS; r += 2) {
        int row = row0 + r;
        if (row >= N_NODES) break;
        bool two = (row + 1 < N_NODES);
        const float4* xa = (const float4*)(x + (size_t)row * IN_DIM);
        const float4* xb = two ? (const float4*)(x + (size_t)(row + 1) * IN_DIM) : xa;
        float acc0 = 0.f, acc1 = 0.f;
#pragma unroll
        for (int k4 = 0; k4 < IN_DIM / 4; ++k4) {
            float4 w = wv[k4];
            float4 a = xa[k4];
            float4 b = xb[k4];
            acc0 += a.x * w.x + a.y * w.y + a.z * w.z + a.w * w.w;
            acc1 += b.x * w.x + b.y * w.y + b.z * w.z + b.w * w.w;
        }
        g_h1[(size_t)row * EMB + col] = acc0;
        if (two) g_h1[(size_t)(row + 1) * EMB + col] = acc1;
    }
}

// layer-1 aggregation: ONE WARP PER NODE, float2 per lane (64 cols).
// Lanes 0..7 cooperatively fetch 8 CSR entries, broadcast via 64-bit shfl,
// then 8 independent gathers per unroll block (MLP=8). Tail entries decode
// to (s=0, w=0.0f) -> harmless. Fused +b1, relu.
__global__ void k_agg1(const float* __restrict__ b1) {
    int node = blockIdx.x * 8 + (threadIdx.x >> 5);
    int lane = threadIdx.x & 31;
    if (node >= N_NODES) return;
    float dn = g_dis[node];
    float2 h0 = ((const float2*)&g_h1[(size_t)node * EMB])[lane];
    float accx = h0.x * dn * dn, accy = h0.y * dn * dn;   // self loop
    int beg = g_rowp[node];
    int cnt = g_cnt [node];
    const long long* p = (const long long*)(g_csr + beg);
    for (int base = 0; base < cnt; base += 8) {
        long long mraw = 0;
        if (lane < 8 && base + lane < cnt) mraw = __ldg(p + base + lane);
#pragma unroll
        for (int j = 0; j < 8; ++j) {
            long long m = __shfl_sync(0xffffffffu, mraw, j);
            int   s = (int)(m & 0xffffffffll);
            float w = __int_as_float((int)(m >> 32));
            float2 h = __ldg((const float2*)&g_h1[(size_t)s * EMB] + lane);
            accx += w * h.x;
            accy += w * h.y;
        }
    }
    float2 bb = ((const float2*)b1)[lane];
    float2 o;
    o.x = fmaxf(accx + bb.x, 0.f);
    o.y = fmaxf(accy + bb.y, 0.f);
    ((float2*)&g_r1[(size_t)node * EMB])[lane] = o;
}

// h2 = r1 @ W2 (100000x64 @ 64x18); W2 transposed in smem -> both operands LDS.128
__global__ void k_gemm2(const float* __restrict__ W2) {
    __shared__ float sA [16 * EMB];
    __shared__ float sWt[NCLS * EMB];    // sWt[c*64 + k]
    int t = threadIdx.y * NCLS + threadIdx.x;  // 0..287
    int node0 = blockIdx.x * 16;
    for (int idx = t; idx < 16 * EMB; idx += 16 * NCLS) {
        int r = idx >> 6, cc = idx & 63;
        int node = node0 + r;
        sA[idx] = (node < N_NODES) ? g_r1[(size_t)node * EMB + cc] : 0.f;
    }
    for (int idx = t; idx < EMB * NCLS; idx += 16 * NCLS) {
        int k = idx / NCLS, c = idx % NCLS;
        sWt[c * EMB + k] = W2[idx];
    }
    __syncthreads();
    int c    = threadIdx.x;        // 0..17
    int node = node0 + threadIdx.y;
    if (node >= N_NODES) return;
    const float4* av = (const float4*)&sA [threadIdx.y * EMB];
    const float4* wv = (const float4*)&sWt[c * EMB];
    float acc = 0.f;
#pragma unroll
    for (int k4 = 0; k4 < EMB / 4; ++k4) {
        float4 a = av[k4];
        float4 w = wv[k4];
        acc += a.x * w.x + a.y * w.y + a.z * w.z + a.w * w.w;
    }
    g_h2[(size_t)node * NCLS + c] = acc;
}

// layer-2 aggregation fused with +b2 and log_softmax. Warp per node,
// same lane-cooperative meta broadcast as k_agg1.
__global__ void k_agg2_final(const float* __restrict__ b2, float* __restrict__ out,
                             int write_logits) {
    int node = blockIdx.x * 8 + (threadIdx.x >> 5);
    int lane = threadIdx.x & 31;
    if (node >= N_NODES) return;
    bool act = lane < NCLS;
    float dn  = g_dis[node];
    float acc = act ? g_h2[(size_t)node * NCLS + lane] * dn * dn : 0.f;
    int beg = g_rowp[node];
    int cnt = g_cnt [node];
    const long long* p = (const long long*)(g_csr + beg);
    for (int base = 0; base < cnt; base += 8) {
        long long mraw = 0;
        if (lane < 8 && base + lane < cnt) mraw = __ldg(p + base + lane);
#pragma unroll
        for (int j = 0; j < 8; ++j) {
            long long m = __shfl_sync(0xffffffffu, mraw, j);
            int   s = (int)(m & 0xffffffffll);
            float w = __int_as_float((int)(m >> 32));
            if (act) acc += w * __ldg(&g_h2[(size_t)s * NCLS + lane]);
        }
    }
    float v = acc + (act ? b2[lane] : 0.f);
    float mx = act ? v : -1e30f;
#pragma unroll
    for (int off = 16; off >= 1; off >>= 1)
        mx = fmaxf(mx, __shfl_xor_sync(0xffffffffu, mx, off));
    float s = act ? __expf(v - mx) : 0.f;
#pragma unroll
    for (int off = 16; off >= 1; off >>= 1)
        s += __shfl_xor_sync(0xffffffffu, s, off);
    float lse = mx + __logf(s);
    if (act) {
        out[(size_t)node * NCLS + lane] = v - lse;
        if (write_logits)
            out[(size_t)N_NODES * NCLS + (size_t)node * NCLS + lane] = v;
    }
}

// ---------------- launch -----------------------------------------------------
extern "C" void kernel_launch(void* const* d_in, const int* in_sizes, int n_in,
                              void* d_out, int out_size) {
    const float* x  = (const float*)d_in[0];
    const int*   ei = (const int*)d_in[1];     // int64 downcast to int32 by harness
    const float* W1 = (const float*)d_in[2];
    const float* b1 = (const float*)d_in[3];
    const float* W2 = (const float*)d_in[4];
    const float* b2 = (const float*)d_in[5];
    float* out = (float*)d_out;

    int E = in_sizes[1] / 2;
    if (E > MAX_E) E = MAX_E;
    int write_logits = (out_size >= 2 * N_NODES * NCLS) ? 1 : 0;

    k_zero<<<(N_NODES + 255) / 256, 256>>>();
    k_deg <<<(E + 255) / 256, 256>>>(ei, E);
    k_scan<<<1, 1024>>>();
    k_fill<<<(E + 255) / 256, 256>>>(ei, E);

    k_gemm1<<<(N_NODES + G1_ROWS - 1) / G1_ROWS, EMB>>>(x, W1);
    k_agg1 <<<(N_NODES + 7) / 8, 256>>>(b1);

    k_gemm2<<<(N_NODES + 15) / 16, dim3(NCLS, 16)>>>(W2);
    k_agg2_final<<<(N_NODES + 7) / 8, 256>>>(b2, out, write_logits);
}

// round 6
// speedup vs baseline: 1.1661x; 1.1661x over previous
#include <cuda_runtime.h>
#include <cstdint>

#define N_NODES 100000
#define IN_DIM  128
#define EMB     64
#define NCLS    18
#define MAX_E   3200000

// ---------------- scratch (static device globals; no allocs) ----------------
__device__ int   g_cnt [N_NODES];     // in-degree (excl self loop)
__device__ int   g_rowp[N_NODES];     // CSR row start
__device__ int   g_cur [N_NODES];     // fill cursor
__device__ float g_dis [N_NODES];     // rsqrt(deg incl self loop)
__device__ float g_h1  [N_NODES * EMB];
__device__ float g_r1  [N_NODES * EMB];   // relu(agg1 + b1)
__device__ float g_h2  [N_NODES * NCLS];
__device__ int2  g_csr [MAX_E];       // (src, bitcast norm), dst-sorted

// ---------------- kernels ---------------------------------------------------

// in-degree count (edge_index is int32 per harness dtype rules)
__global__ void k_deg(const int* __restrict__ ei, int E) {
    int e = blockIdx.x * blockDim.x + threadIdx.x;
    if (e < E) {
        int d = __ldg(ei + E + e);
        if ((unsigned)d < N_NODES) atomicAdd(&g_cnt[d], 1);
    }
}

// single-block exclusive scan over g_cnt -> g_rowp/g_cur; also g_dis
__global__ void k_scan() {
    __shared__ int ssum[1024];
    const int CH = (N_NODES + 1023) / 1024;   // 98
    int t  = threadIdx.x;
    int lo = t * CH;
    int hi = min(lo + CH, N_NODES);
    int s = 0;
    for (int i = lo; i < hi; ++i) s += g_cnt[i];
    ssum[t] = s;
    __syncthreads();
    for (int off = 1; off < 1024; off <<= 1) {
        int u = (t >= off) ? ssum[t - off] : 0;
        __syncthreads();
        ssum[t] += u;
        __syncthreads();
    }
    int run = ssum[t] - s;   // exclusive base for this thread's chunk
    for (int i = lo; i < hi; ++i) {
        int c = g_cnt[i];
        g_rowp[i] = run;
        g_cur [i] = run;
        g_dis [i] = rsqrtf((float)(c + 1));
        run += c;
    }
}

// scatter (src, norm) into dst-sorted CSR slots
__global__ void k_fill(const int* __restrict__ ei, int E) {
    int e = blockIdx.x * blockDim.x + threadIdx.x;
    if (e >= E) return;
    int s = __ldg(ei + e);
    int d = __ldg(ei + E + e);
    if ((unsigned)s >= N_NODES) s = 0;
    if ((unsigned)d >= N_NODES) d = 0;
    float nrm = g_dis[s] * g_dis[d];
    int pos = atomicAdd(&g_cur[d], 1);
    g_csr[pos] = make_int2(s, __float_as_int(nrm));
}

// h1 = x @ W1  (100000x128 @ 128x64). W1 transposed in smem for LDS.128;
// thread owns one column, 4 rows per iteration reuse each weight vector.
#define G1_ROWS 64
__global__ void k_gemm1(const float* __restrict__ x, const float* __restrict__ W1) {
    __shared__ float sWt[EMB * IN_DIM];  // sWt[c*128 + k], 32 KB
    for (int i = threadIdx.x; i < IN_DIM * EMB; i += blockDim.x) {
        int k = i >> 6, c = i & 63;      // W1 is [128,64] row-major
        sWt[c * IN_DIM + k] = W1[i];
    }
    __syncthreads();
    int col  = threadIdx.x;                   // 0..63
    int row0 = blockIdx.x * G1_ROWS;
    const float4* wv = (const float4*)&sWt[col * IN_DIM];
    for (int r = 0; r < G1_ROWS; r += 4) {
        int row = row0 + r;
        if (row >= N_NODES) break;
        int nr = min(4, N_NODES - row);
        const float4* xp0 = (const float4*)(x + (size_t)row * IN_DIM);
        const float4* xp1 = (const float4*)(x + (size_t)(row + (nr > 1 ? 1 : 0)) * IN_DIM);
        const float4* xp2 = (const float4*)(x + (size_t)(row + (nr > 2 ? 2 : 0)) * IN_DIM);
        const float4* xp3 = (const float4*)(x + (size_t)(row + (nr > 3 ? 3 : 0)) * IN_DIM);
        float a0 = 0.f, a1 = 0.f, a2 = 0.f, a3 = 0.f;
#pragma unroll
        for (int k4 = 0; k4 < IN_DIM / 4; ++k4) {
            float4 w = wv[k4];
            float4 v0 = xp0[k4], v1 = xp1[k4], v2 = xp2[k4], v3 = xp3[k4];
            a0 += v0.x * w.x + v0.y * w.y + v0.z * w.z + v0.w * w.w;
            a1 += v1.x * w.x + v1.y * w.y + v1.z * w.z + v1.w * w.w;
            a2 += v2.x * w.x + v2.y * w.y + v2.z * w.z + v2.w * w.w;
            a3 += v3.x * w.x + v3.y * w.y + v3.z * w.z + v3.w * w.w;
        }
        g_h1[(size_t)row * EMB + col] = a0;
        if (nr > 1) g_h1[(size_t)(row + 1) * EMB + col] = a1;
        if (nr > 2) g_h1[(size_t)(row + 2) * EMB + col] = a2;
        if (nr > 3) g_h1[(size_t)(row + 3) * EMB + col] = a3;
    }
}

// layer-1 aggregation: WARP PER NODE, float2 per lane (64 cols).
// Meta staged 32-at-a-time into smem with ONE coalesced 256B warp load,
// then broadcast LDS feeds unroll-4 independent gathers. Fused +b1, relu.
__global__ void k_agg1(const float* __restrict__ b1) {
    __shared__ long long smeta[8][32];
    int g    = threadIdx.x >> 5;          // warp in block, 0..7
    int lane = threadIdx.x & 31;
    int node = blockIdx.x * 8 + g;
    if (node >= N_NODES) return;          // warp-uniform exit
    float dn = g_dis[node];
    float2 h0 = __ldg((const float2*)&g_h1[(size_t)node * EMB] + lane);
    float ax = h0.x * dn * dn, ay = h0.y * dn * dn;   // self loop
    int beg = g_rowp[node];
    int cnt = g_cnt [node];
    const long long* p = (const long long*)(g_csr + beg);
    for (int base = 0; base < cnt; base += 32) {
        int m = min(32, cnt - base);
        if (lane < m) smeta[g][lane] = __ldg(p + base + lane);
        __syncwarp();
#pragma unroll 4
        for (int j = 0; j < m; ++j) {
            long long mv = smeta[g][j];              // broadcast LDS
            int   s = (int)(mv & 0xffffffffll);
            float w = __int_as_float((int)(mv >> 32));
            float2 h = __ldg((const float2*)&g_h1[(size_t)s * EMB] + lane);
            ax += w * h.x;
            ay += w * h.y;
        }
        __syncwarp();
    }
    float2 bb = __ldg((const float2*)b1 + lane);
    float2 o;
    o.x = fmaxf(ax + bb.x, 0.f);
    o.y = fmaxf(ay + bb.y, 0.f);
    ((float2*)&g_r1[(size_t)node * EMB])[lane] = o;
}

// h2 = r1 @ W2 (100000x64 @ 64x18); W2 transposed in smem -> both operands LDS.128
__global__ void k_gemm2(const float* __restrict__ W2) {
    __shared__ float sA [16 * EMB];
    __shared__ float sWt[NCLS * EMB];    // sWt[c*64 + k]
    int t = threadIdx.y * NCLS + threadIdx.x;  // 0..287
    int node0 = blockIdx.x * 16;
    for (int idx = t; idx < 16 * EMB; idx += 16 * NCLS) {
        int r = idx >> 6, cc = idx & 63;
        int node = node0 + r;
        sA[idx] = (node < N_NODES) ? g_r1[(size_t)node * EMB + cc] : 0.f;
    }
    for (int idx = t; idx < EMB * NCLS; idx += 16 * NCLS) {
        int k = idx / NCLS, c = idx % NCLS;
        sWt[c * EMB + k] = W2[idx];
    }
    __syncthreads();
    int c    = threadIdx.x;        // 0..17
    int node = node0 + threadIdx.y;
    if (node >= N_NODES) return;
    const float4* av = (const float4*)&sA [threadIdx.y * EMB];
    const float4* wv = (const float4*)&sWt[c * EMB];
    float acc = 0.f;
#pragma unroll
    for (int k4 = 0; k4 < EMB / 4; ++k4) {
        float4 a = av[k4];
        float4 w = wv[k4];
        acc += a.x * w.x + a.y * w.y + a.z * w.z + a.w * w.w;
    }
    g_h2[(size_t)node * NCLS + c] = acc;
}

// layer-2 aggregation fused with +b2 and log_softmax. Warp per node,
// same smem meta staging as k_agg1.
__global__ void k_agg2_final(const float* __restrict__ b2, float* __restrict__ out,
                             int write_logits) {
    __shared__ long long smeta[8][32];
    int g    = threadIdx.x >> 5;
    int lane = threadIdx.x & 31;
    int node = blockIdx.x * 8 + g;
    if (node >= N_NODES) return;          // warp-uniform exit
    bool act = lane < NCLS;
    float dn  = g_dis[node];
    float acc = act ? g_h2[(size_t)node * NCLS + lane] * dn * dn : 0.f;
    int beg = g_rowp[node];
    int cnt = g_cnt [node];
    const long long* p = (const long long*)(g_csr + beg);
    for (int base = 0; base < cnt; base += 32) {
        int m = min(32, cnt - base);
        if (lane < m) smeta[g][lane] = __ldg(p + base + lane);
        __syncwarp();
#pragma unroll 4
        for (int j = 0; j < m; ++j) {
            long long mv = smeta[g][j];
            int   s = (int)(mv & 0xffffffffll);
            float w = __int_as_float((int)(mv >> 32));
            if (act) acc += w * __ldg(&g_h2[(size_t)s * NCLS + lane]);
        }
        __syncwarp();
    }
    float v = acc + (act ? b2[lane] : 0.f);
    float mx = act ? v : -1e30f;
#pragma unroll
    for (int off = 16; off >= 1; off >>= 1)
        mx = fmaxf(mx, __shfl_xor_sync(0xffffffffu, mx, off));
    float s = act ? __expf(v - mx) : 0.f;
#pragma unroll
    for (int off = 16; off >= 1; off >>= 1)
        s += __shfl_xor_sync(0xffffffffu, s, off);
    float lse = mx + __logf(s);
    if (act) {
        out[(size_t)node * NCLS + lane] = v - lse;
        if (write_logits)
            out[(size_t)N_NODES * NCLS + (size_t)node * NCLS + lane] = v;
    }
}

// ---------------- launch -----------------------------------------------------
extern "C" void kernel_launch(void* const* d_in, const int* in_sizes, int n_in,
                              void* d_out, int out_size) {
    const float* x  = (const float*)d_in[0];
    const int*   ei = (const int*)d_in[1];     // int64 downcast to int32 by harness
    const float* W1 = (const float*)d_in[2];
    const float* b1 = (const float*)d_in[3];
    const float* W2 = (const float*)d_in[4];
    const float* b2 = (const float*)d_in[5];
    float* out = (float*)d_out;

    int E = in_sizes[1] / 2;
    if (E > MAX_E) E = MAX_E;
    int write_logits = (out_size >= 2 * N_NODES * NCLS) ? 1 : 0;

    void* cnt_ptr = nullptr;
    cudaGetSymbolAddress(&cnt_ptr, g_cnt);
    cudaMemsetAsync(cnt_ptr, 0, N_NODES * sizeof(int));   // memset node, not a launch

    k_deg <<<(E + 255) / 256, 256>>>(ei, E);
    k_scan<<<1, 1024>>>();
    k_fill<<<(E + 255) / 256, 256>>>(ei, E);

    k_gemm1<<<(N_NODES + G1_ROWS - 1) / G1_ROWS, EMB>>>(x, W1);   // 4th launch -> profiled
    k_agg1 <<<(N_NODES + 7) / 8, 256>>>(b1);

    k_gemm2<<<(N_NODES + 15) / 16, dim3(NCLS, 16)>>>(W2);
    k_agg2_final<<<(N_NODES + 7) / 8, 256>>>(b2, out, write_logits);
}

// round 7
// speedup vs baseline: 1.2407x; 1.0640x over previous
#include <cuda_runtime.h>
#include <cstdint>

#define N_NODES 100000
#define IN_DIM  128
#define EMB     64
#define NCLS    18
#define MAX_E   3200000

// ---------------- scratch (static device globals; no allocs) ----------------
__device__ int   g_cnt [N_NODES];     // in-degree (excl self loop)
__device__ int   g_rowp[N_NODES];     // CSR row start
__device__ int   g_cur [N_NODES];     // fill cursor
__device__ float g_dis [N_NODES];     // rsqrt(deg incl self loop)
__device__ float g_h1  [N_NODES * EMB];
__device__ float g_r1  [N_NODES * EMB];   // relu(agg1 + b1)
__device__ float g_h2  [N_NODES * NCLS];
__device__ int2  g_csr [MAX_E];       // (src, bitcast norm), dst-sorted

// ---------------- kernels ---------------------------------------------------

// in-degree count (edge_index is int32 per harness dtype rules)
__global__ void k_deg(const int* __restrict__ ei, int E) {
    int e = blockIdx.x * blockDim.x + threadIdx.x;
    if (e < E) {
        int d = __ldg(ei + E + e);
        if ((unsigned)d < N_NODES) atomicAdd(&g_cnt[d], 1);
    }
}

// single-block exclusive scan over g_cnt -> g_rowp/g_cur; also g_dis
__global__ void k_scan() {
    __shared__ int ssum[1024];
    const int CH = (N_NODES + 1023) / 1024;   // 98
    int t  = threadIdx.x;
    int lo = t * CH;
    int hi = min(lo + CH, N_NODES);
    int s = 0;
    for (int i = lo; i < hi; ++i) s += g_cnt[i];
    ssum[t] = s;
    __syncthreads();
    for (int off = 1; off < 1024; off <<= 1) {
        int u = (t >= off) ? ssum[t - off] : 0;
        __syncthreads();
        ssum[t] += u;
        __syncthreads();
    }
    int run = ssum[t] - s;   // exclusive base for this thread's chunk
    for (int i = lo; i < hi; ++i) {
        int c = g_cnt[i];
        g_rowp[i] = run;
        g_cur [i] = run;
        g_dis [i] = rsqrtf((float)(c + 1));
        run += c;
    }
}

// scatter (src, norm) into dst-sorted CSR slots
__global__ void k_fill(const int* __restrict__ ei, int E) {
    int e = blockIdx.x * blockDim.x + threadIdx.x;
    if (e >= E) return;
    int s = __ldg(ei + e);
    int d = __ldg(ei + E + e);
    if ((unsigned)s >= N_NODES) s = 0;
    if ((unsigned)d >= N_NODES) d = 0;
    float nrm = g_dis[s] * g_dis[d];
    int pos = atomicAdd(&g_cur[d], 1);
    g_csr[pos] = make_int2(s, __float_as_int(nrm));
}

// h1 = x @ W1  (100000x128 @ 128x64). 256-thread blocks = 4 independent
// 64-row slabs sharing one 32KB transposed-W smem tile. Thread owns one
// output column in its slab; 4 rows per iter reuse each weight vector.
#define G1_BLOCK_ROWS 256
__global__ void k_gemm1(const float* __restrict__ x, const float* __restrict__ W1) {
    __shared__ float sWt[EMB * IN_DIM];  // sWt[c*128 + k], 32 KB
    for (int i = threadIdx.x; i < IN_DIM * EMB; i += blockDim.x) {
        int k = i >> 6, c = i & 63;      // W1 is [128,64] row-major
        sWt[c * IN_DIM + k] = W1[i];
    }
    __syncthreads();
    int grp  = threadIdx.x >> 6;              // 0..3 slab within block
    int col  = threadIdx.x & 63;              // 0..63
    int row0 = blockIdx.x * G1_BLOCK_ROWS + grp * 64;
    const float4* wv = (const float4*)&sWt[col * IN_DIM];
    for (int r = 0; r < 64; r += 4) {
        int row = row0 + r;
        if (row >= N_NODES) break;
        int nr = min(4, N_NODES - row);
        const float4* xp0 = (const float4*)(x + (size_t)row * IN_DIM);
        const float4* xp1 = (const float4*)(x + (size_t)(row + (nr > 1 ? 1 : 0)) * IN_DIM);
        const float4* xp2 = (const float4*)(x + (size_t)(row + (nr > 2 ? 2 : 0)) * IN_DIM);
        const float4* xp3 = (const float4*)(x + (size_t)(row + (nr > 3 ? 3 : 0)) * IN_DIM);
        float a0 = 0.f, a1 = 0.f, a2 = 0.f, a3 = 0.f;
#pragma unroll
        for (int k4 = 0; k4 < IN_DIM / 4; ++k4) {
            float4 w = wv[k4];
            float4 v0 = xp0[k4], v1 = xp1[k4], v2 = xp2[k4], v3 = xp3[k4];
            a0 += v0.x * w.x + v0.y * w.y + v0.z * w.z + v0.w * w.w;
            a1 += v1.x * w.x + v1.y * w.y + v1.z * w.z + v1.w * w.w;
            a2 += v2.x * w.x + v2.y * w.y + v2.z * w.z + v2.w * w.w;
            a3 += v3.x * w.x + v3.y * w.y + v3.z * w.z + v3.w * w.w;
        }
        g_h1[(size_t)row * EMB + col] = a0;
        if (nr > 1) g_h1[(size_t)(row + 1) * EMB + col] = a1;
        if (nr > 2) g_h1[(size_t)(row + 2) * EMB + col] = a2;
        if (nr > 3) g_h1[(size_t)(row + 3) * EMB + col] = a3;
    }
}

// layer-1 aggregation (gather over CSR) fused with +b1, relu.
// 64-thread group per node, thread owns one column. (R4-measured best shape.)
__global__ void k_agg1(const float* __restrict__ b1) {
    int node = blockIdx.x * 4 + (threadIdx.x >> 6);
    int c    = threadIdx.x & 63;
    if (node >= N_NODES) return;
    float dn  = g_dis[node];
    float acc = g_h1[(size_t)node * EMB + c] * dn * dn;   // self loop
    float acc2 = 0.f;
    int beg = g_rowp[node];
    int cnt = g_cnt [node];
    const int2* p = g_csr + beg;
    int i = 0;
    for (; i + 2 <= cnt; i += 2) {
        int2 m0 = __ldg(p + i);
        int2 m1 = __ldg(p + i + 1);
        acc  += __int_as_float(m0.y) * __ldg(&g_h1[(size_t)m0.x * EMB + c]);
        acc2 += __int_as_float(m1.y) * __ldg(&g_h1[(size_t)m1.x * EMB + c]);
    }
    if (i < cnt) {
        int2 m = __ldg(p + i);
        acc += __int_as_float(m.y) * __ldg(&g_h1[(size_t)m.x * EMB + c]);
    }
    g_r1[(size_t)node * EMB + c] = fmaxf(acc + acc2 + b1[c], 0.f);
}

// h2 = r1 @ W2 (100000x64 @ 64x18); W2 transposed in smem -> both operands LDS.128
__global__ void k_gemm2(const float* __restrict__ W2) {
    __shared__ float sA [16 * EMB];
    __shared__ float sWt[NCLS * EMB];    // sWt[c*64 + k]
    int t = threadIdx.y * NCLS + threadIdx.x;  // 0..287
    int node0 = blockIdx.x * 16;
    for (int idx = t; idx < 16 * EMB; idx += 16 * NCLS) {
        int r = idx >> 6, cc = idx & 63;
        int node = node0 + r;
        sA[idx] = (node < N_NODES) ? g_r1[(size_t)node * EMB + cc] : 0.f;
    }
    for (int idx = t; idx < EMB * NCLS; idx += 16 * NCLS) {
        int k = idx / NCLS, c = idx % NCLS;
        sWt[c * EMB + k] = W2[idx];
    }
    __syncthreads();
    int c    = threadIdx.x;        // 0..17
    int node = node0 + threadIdx.y;
    if (node >= N_NODES) return;
    const float4* av = (const float4*)&sA [threadIdx.y * EMB];
    const float4* wv = (const float4*)&sWt[c * EMB];
    float acc = 0.f;
#pragma unroll
    for (int k4 = 0; k4 < EMB / 4; ++k4) {
        float4 a = av[k4];
        float4 w = wv[k4];
        acc += a.x * w.x + a.y * w.y + a.z * w.z + a.w * w.w;
    }
    g_h2[(size_t)node * NCLS + c] = acc;
}

// layer-2 aggregation fused with +b2 and log_softmax. Warp per node.
// (R4-measured best shape: warp-uniform meta __ldg broadcast.)
__global__ void k_agg2_final(const float* __restrict__ b2, float* __restrict__ out,
                             int write_logits) {
    int node = blockIdx.x * 8 + (threadIdx.x >> 5);
    int lane = threadIdx.x & 31;
    if (node >= N_NODES) return;
    bool act = lane < NCLS;
    float dn  = g_dis[node];
    float acc = act ? g_h2[(size_t)node * NCLS + lane] * dn * dn : 0.f;
    int beg = g_rowp[node];
    int cnt = g_cnt [node];
    const int2* p = g_csr + beg;
    float acc2 = 0.f;
    int i = 0;
    for (; i + 2 <= cnt; i += 2) {
        int2 m0 = __ldg(p + i);       // warp-uniform address -> broadcast
        int2 m1 = __ldg(p + i + 1);
        if (act) {
            acc  += __int_as_float(m0.y) * __ldg(&g_h2[(size_t)m0.x * NCLS + lane]);
            acc2 += __int_as_float(m1.y) * __ldg(&g_h2[(size_t)m1.x * NCLS + lane]);
        }
    }
    if (i < cnt) {
        int2 m = __ldg(p + i);
        if (act) acc += __int_as_float(m.y) * __ldg(&g_h2[(size_t)m.x * NCLS + lane]);
    }
    float v = acc + acc2 + (act ? b2[lane] : 0.f);
    float mx = act ? v : -1e30f;
#pragma unroll
    for (int off = 16; off >= 1; off >>= 1)
        mx = fmaxf(mx, __shfl_xor_sync(0xffffffffu, mx, off));
    float s = act ? __expf(v - mx) : 0.f;
#pragma unroll
    for (int off = 16; off >= 1; off >>= 1)
        s += __shfl_xor_sync(0xffffffffu, s, off);
    float lse = mx + __logf(s);
    if (act) {
        out[(size_t)node * NCLS + lane] = v - lse;
        if (write_logits)
            out[(size_t)N_NODES * NCLS + (size_t)node * NCLS + lane] = v;
    }
}

// ---------------- launch -----------------------------------------------------
extern "C" void kernel_launch(void* const* d_in, const int* in_sizes, int n_in,
                              void* d_out, int out_size) {
    const float* x  = (const float*)d_in[0];
    const int*   ei = (const int*)d_in[1];     // int64 downcast to int32 by harness
    const float* W1 = (const float*)d_in[2];
    const float* b1 = (const float*)d_in[3];
    const float* W2 = (const float*)d_in[4];
    const float* b2 = (const float*)d_in[5];
    float* out = (float*)d_out;

    int E = in_sizes[1] / 2;
    if (E > MAX_E) E = MAX_E;
    int write_logits = (out_size >= 2 * N_NODES * NCLS) ? 1 : 0;

    void* cnt_ptr = nullptr;
    cudaGetSymbolAddress(&cnt_ptr, g_cnt);
    cudaMemsetAsync(cnt_ptr, 0, N_NODES * sizeof(int));   // memset node, not a launch

    k_deg <<<(E + 255) / 256, 256>>>(ei, E);
    k_scan<<<1, 1024>>>();
    k_fill<<<(E + 255) / 256, 256>>>(ei, E);

    k_gemm1<<<(N_NODES + G1_BLOCK_ROWS - 1) / G1_BLOCK_ROWS, 256>>>(x, W1); // 4th launch -> profiled
    k_agg1 <<<(N_NODES + 3) / 4, 256>>>(b1);

    k_gemm2<<<(N_NODES + 15) / 16, dim3(NCLS, 16)>>>(W2);
    k_agg2_final<<<(N_NODES + 7) / 8, 256>>>(b2, out, write_logits);
}

// round 9
// speedup vs baseline: 1.7243x; 1.3898x over previous
#include <cuda_runtime.h>
#include <cstdint>

#define N_NODES 100000
#define IN_DIM  128
#define EMB     64
#define NCLS    18
#define MAX_E   3200000

// ---------------- scratch (static device globals; no allocs) ----------------
__device__ int   g_cnt [N_NODES];     // in-degree (excl self loop)
__device__ int   g_rowp[N_NODES];     // CSR row start
__device__ int   g_cur [N_NODES];     // fill cursor
__device__ float g_dis [N_NODES];     // rsqrt(deg incl self loop)
__device__ float g_h1  [N_NODES * EMB];
__device__ float g_r1  [N_NODES * EMB];   // relu(agg1 + b1)
__device__ float g_h2  [N_NODES * NCLS];
__device__ int2  g_csr [MAX_E];       // (src, bitcast norm), dst-sorted

// ---------------- kernels ---------------------------------------------------

// in-degree count (edge_index is int32 per harness dtype rules)
__global__ void k_deg(const int* __restrict__ ei, int E) {
    int e = blockIdx.x * blockDim.x + threadIdx.x;
    if (e < E) {
        int d = __ldg(ei + E + e);
        if ((unsigned)d < N_NODES) atomicAdd(&g_cnt[d], 1);
    }
}

// single-block exclusive scan over g_cnt -> g_rowp/g_cur; also g_dis
__global__ void k_scan() {
    __shared__ int ssum[1024];
    const int CH = (N_NODES + 1023) / 1024;   // 98
    int t  = threadIdx.x;
    int lo = t * CH;
    int hi = min(lo + CH, N_NODES);
    int s = 0;
    for (int i = lo; i < hi; ++i) s += g_cnt[i];
    ssum[t] = s;
    __syncthreads();
    for (int off = 1; off < 1024; off <<= 1) {
        int u = (t >= off) ? ssum[t - off] : 0;
        __syncthreads();
        ssum[t] += u;
        __syncthreads();
    }
    int run = ssum[t] - s;   // exclusive base for this thread's chunk
    for (int i = lo; i < hi; ++i) {
        int c = g_cnt[i];
        g_rowp[i] = run;
        g_cur [i] = run;
        g_dis [i] = rsqrtf((float)(c + 1));
        run += c;
    }
}

// scatter (src, norm) into dst-sorted CSR slots
__global__ void k_fill(const int* __restrict__ ei, int E) {
    int e = blockIdx.x * blockDim.x + threadIdx.x;
    if (e >= E) return;
    int s = __ldg(ei + e);
    int d = __ldg(ei + E + e);
    if ((unsigned)s >= N_NODES) s = 0;
    if ((unsigned)d >= N_NODES) d = 0;
    float nrm = g_dis[s] * g_dis[d];
    int pos = atomicAdd(&g_cur[d], 1);
    g_csr[pos] = make_int2(s, __float_as_int(nrm));
}

// h1 = x @ W1  (100000x128 @ 128x64).
// Weight tile transposed in smem with XOR swizzle on the float4 index:
// column c's k4-th float4 lives at slot (k4 ^ (c&7)) -> LDS.128 is
// bank-conflict-free across each 8-lane phase. 256 threads = 4 slabs of
// 32 rows; each thread owns one column, 4 rows per iter reuse each w vector.
#define G1_BLOCK_ROWS 128
__global__ void k_gemm1(const float* __restrict__ x, const float* __restrict__ W1) {
    __shared__ float sWt[EMB * IN_DIM];  // 32 KB, swizzled float4 layout
    for (int i = threadIdx.x; i < IN_DIM * EMB; i += blockDim.x) {
        int k = i >> 6, c = i & 63;      // W1 is [128,64] row-major
        int k4 = k >> 2, j = k & 3;
        sWt[(c * 32 + (k4 ^ (c & 7))) * 4 + j] = W1[i];
    }
    __syncthreads();
    int grp  = threadIdx.x >> 6;              // 0..3 slab within block
    int col  = threadIdx.x & 63;              // 0..63
    int sw   = col & 7;
    int row0 = blockIdx.x * G1_BLOCK_ROWS + grp * 32;
    const float4* wv = (const float4*)&sWt[col * IN_DIM];
    for (int r = 0; r < 32; r += 4) {
        int row = row0 + r;
        if (row >= N_NODES) break;
        int nr = min(4, N_NODES - row);
        const float4* xp0 = (const float4*)(x + (size_t)row * IN_DIM);
        const float4* xp1 = (const float4*)(x + (size_t)(row + (nr > 1 ? 1 : 0)) * IN_DIM);
        const float4* xp2 = (const float4*)(x + (size_t)(row + (nr > 2 ? 2 : 0)) * IN_DIM);
        const float4* xp3 = (const float4*)(x + (size_t)(row + (nr > 3 ? 3 : 0)) * IN_DIM);
        float a0 = 0.f, a1 = 0.f, a2 = 0.f, a3 = 0.f;
#pragma unroll
        for (int k4 = 0; k4 < IN_DIM / 4; ++k4) {
            float4 w = wv[k4 ^ sw];
            float4 v0 = xp0[k4], v1 = xp1[k4], v2 = xp2[k4], v3 = xp3[k4];
            a0 += v0.x * w.x + v0.y * w.y + v0.z * w.z + v0.w * w.w;
            a1 += v1.x * w.x + v1.y * w.y + v1.z * w.z + v1.w * w.w;
            a2 += v2.x * w.x + v2.y * w.y + v2.z * w.z + v2.w * w.w;
            a3 += v3.x * w.x + v3.y * w.y + v3.z * w.z + v3.w * w.w;
        }
        g_h1[(size_t)row * EMB + col] = a0;
        if (nr > 1) g_h1[(size_t)(row + 1) * EMB + col] = a1;
        if (nr > 2) g_h1[(size_t)(row + 2) * EMB + col] = a2;
        if (nr > 3) g_h1[(size_t)(row + 3) * EMB + col] = a3;
    }
}

// layer-1 aggregation (gather over CSR) fused with +b1, relu.
// 64-thread group per node, thread owns one column. (R4-measured best shape.)
__global__ void k_agg1(const float* __restrict__ b1) {
    int node = blockIdx.x * 4 + (threadIdx.x >> 6);
    int c    = threadIdx.x & 63;
    if (node >= N_NODES) return;
    float dn  = g_dis[node];
    float acc = g_h1[(size_t)node * EMB + c] * dn * dn;   // self loop
    float acc2 = 0.f;
    int beg = g_rowp[node];
    int cnt = g_cnt [node];
    const int2* p = g_csr + beg;
    int i = 0;
    for (; i + 2 <= cnt; i += 2) {
        int2 m0 = __ldg(p + i);
        int2 m1 = __ldg(p + i + 1);
        acc  += __int_as_float(m0.y) * __ldg(&g_h1[(size_t)m0.x * EMB + c]);
        acc2 += __int_as_float(m1.y) * __ldg(&g_h1[(size_t)m1.x * EMB + c]);
    }
    if (i < cnt) {
        int2 m = __ldg(p + i);
        acc += __int_as_float(m.y) * __ldg(&g_h1[(size_t)m.x * EMB + c]);
    }
    g_r1[(size_t)node * EMB + c] = fmaxf(acc + acc2 + b1[c], 0.f);
}

// h2 = r1 @ W2 (100000x64 @ 64x18). R4 scalar form: sW[k*NCLS+c] puts
// consecutive c in consecutive banks (conflict-free); sA reads broadcast.
__global__ void k_gemm2(const float* __restrict__ W2) {
    __shared__ float sA[16 * EMB];
    __shared__ float sW[EMB * NCLS];
    int t = threadIdx.y * NCLS + threadIdx.x;  // 0..287
    int node0 = blockIdx.x * 16;
    for (int idx = t; idx < 16 * EMB; idx += 16 * NCLS) {
        int r = idx >> 6, cc = idx & 63;
        int node = node0 + r;
        sA[idx] = (node < N_NODES) ? g_r1[(size_t)node * EMB + cc] : 0.f;
    }
    for (int idx = t; idx < EMB * NCLS; idx += 16 * NCLS) sW[idx] = W2[idx];
    __syncthreads();
    int c    = threadIdx.x;        // 0..17
    int node = node0 + threadIdx.y;
    if (node >= N_NODES) return;
    float acc = 0.f;
#pragma unroll
    for (int k = 0; k < EMB; ++k) acc += sA[threadIdx.y * EMB + k] * sW[k * NCLS + c];
    g_h2[(size_t)node * NCLS + c] = acc;
}

// layer-2 aggregation fused with +b2 and log_softmax. Warp per node.
// (R4-measured best shape: warp-uniform meta __ldg broadcast.)
__global__ void k_agg2_final(const float* __restrict__ b2, float* __restrict__ out,
                             int write_logits) {
    int node = blockIdx.x * 8 + (threadIdx.x >> 5);
    int lane = threadIdx.x & 31;
    if (node >= N_NODES) return;
    bool act = lane < NCLS;
    float dn  = g_dis[node];
    float acc = act ? g_h2[(size_t)node * NCLS + lane] * dn * dn : 0.f;
    int beg = g_rowp[node];
    int cnt = g_cnt [node];
    const int2* p = g_csr + beg;
    float acc2 = 0.f;
    int i = 0;
    for (; i + 2 <= cnt; i += 2) {
        int2 m0 = __ldg(p + i);       // warp-uniform address -> broadcast
        int2 m1 = __ldg(p + i + 1);
        if (act) {
            acc  += __int_as_float(m0.y) * __ldg(&g_h2[(size_t)m0.x * NCLS + lane]);
            acc2 += __int_as_float(m1.y) * __ldg(&g_h2[(size_t)m1.x * NCLS + lane]);
        }
    }
    if (i < cnt) {
        int2 m = __ldg(p + i);
        if (act) acc += __int_as_float(m.y) * __ldg(&g_h2[(size_t)m.x * NCLS + lane]);
    }
    float v = acc + acc2 + (act ? b2[lane] : 0.f);
    float mx = act ? v : -1e30f;
#pragma unroll
    for (int off = 16; off >= 1; off >>= 1)
        mx = fmaxf(mx, __shfl_xor_sync(0xffffffffu, mx, off));
    float s = act ? __expf(v - mx) : 0.f;
#pragma unroll
    for (int off = 16; off >= 1; off >>= 1)
        s += __shfl_xor_sync(0xffffffffu, s, off);
    float lse = mx + __logf(s);
    if (act) {
        out[(size_t)node * NCLS + lane] = v - lse;
        if (write_logits)
            out[(size_t)N_NODES * NCLS + (size_t)node * NCLS + lane] = v;
    }
}

// ---------------- launch -----------------------------------------------------
extern "C" void kernel_launch(void* const* d_in, const int* in_sizes, int n_in,
                              void* d_out, int out_size) {
    const float* x  = (const float*)d_in[0];
    const int*   ei = (const int*)d_in[1];     // int64 downcast to int32 by harness
    const float* W1 = (const float*)d_in[2];
    const float* b1 = (const float*)d_in[3];
    const float* W2 = (const float*)d_in[4];
    const float* b2 = (const float*)d_in[5];
    float* out = (float*)d_out;

    int E = in_sizes[1] / 2;
    if (E > MAX_E) E = MAX_E;
    int write_logits = (out_size >= 2 * N_NODES * NCLS) ? 1 : 0;

    void* cnt_ptr = nullptr;
    cudaGetSymbolAddress(&cnt_ptr, g_cnt);
    cudaMemsetAsync(cnt_ptr, 0, N_NODES * sizeof(int));   // memset node, not a launch

    k_deg <<<(E + 255) / 256, 256>>>(ei, E);
    k_scan<<<1, 1024>>>();
    k_fill<<<(E + 255) / 256, 256>>>(ei, E);

    k_gemm1<<<(N_NODES + G1_BLOCK_ROWS - 1) / G1_BLOCK_ROWS, 256>>>(x, W1); // 4th launch -> profiled
    k_agg1 <<<(N_NODES + 3) / 4, 256>>>(b1);

    k_gemm2<<<(N_NODES + 15) / 16, dim3(NCLS, 16)>>>(W2);
    k_agg2_final<<<(N_NODES + 7) / 8, 256>>>(b2, out, write_logits);
}

// round 11
// speedup vs baseline: 2.0363x; 1.1809x over previous
#include <cuda_runtime.h>
#include <cstdint>

#define N_NODES 100000
#define IN_DIM  128
#define EMB     64
#define NCLS    18
#define MAX_E   3200000

// ---------------- scratch (static device globals; no allocs) ----------------
__device__ int   g_cnt [N_NODES];     // in-degree (excl self loop)
__device__ int   g_rowp[N_NODES];     // CSR row start
__device__ int   g_cur [N_NODES];     // fill cursor
__device__ float g_dis [N_NODES];     // rsqrt(deg incl self loop)
__device__ float g_h1  [N_NODES * EMB];
__device__ float g_r1  [N_NODES * EMB];   // relu(agg1 + b1)
__device__ float g_h2  [N_NODES * NCLS];
__device__ int4  g_csr4[MAX_E / 2 + 1];   // 16B-aligned backing for CSR
#define g_csr ((int2*)g_csr4)             // (src, bitcast norm), dst-sorted

// ---------------- kernels ---------------------------------------------------

// in-degree count (edge_index is int32 per harness dtype rules)
__global__ void k_deg(const int* __restrict__ ei, int E) {
    int e = blockIdx.x * blockDim.x + threadIdx.x;
    if (e < E) {
        int d = __ldg(ei + E + e);
        if ((unsigned)d < N_NODES) atomicAdd(&g_cnt[d], 1);
    }
}

// single-block exclusive scan over g_cnt -> g_rowp/g_cur; also g_dis
__global__ void k_scan() {
    __shared__ int ssum[1024];
    const int CH = (N_NODES + 1023) / 1024;   // 98
    int t  = threadIdx.x;
    int lo = t * CH;
    int hi = min(lo + CH, N_NODES);
    int s = 0;
    for (int i = lo; i < hi; ++i) s += g_cnt[i];
    ssum[t] = s;
    __syncthreads();
    for (int off = 1; off < 1024; off <<= 1) {
        int u = (t >= off) ? ssum[t - off] : 0;
        __syncthreads();
        ssum[t] += u;
        __syncthreads();
    }
    int run = ssum[t] - s;   // exclusive base for this thread's chunk
    for (int i = lo; i < hi; ++i) {
        int c = g_cnt[i];
        g_rowp[i] = run;
        g_cur [i] = run;
        g_dis [i] = rsqrtf((float)(c + 1));
        run += c;
    }
}

// scatter (src, norm) into dst-sorted CSR slots
__global__ void k_fill(const int* __restrict__ ei, int E) {
    int e = blockIdx.x * blockDim.x + threadIdx.x;
    if (e >= E) return;
    int s = __ldg(ei + e);
    int d = __ldg(ei + E + e);
    if ((unsigned)s >= N_NODES) s = 0;
    if ((unsigned)d >= N_NODES) d = 0;
    float nrm = g_dis[s] * g_dis[d];
    int pos = atomicAdd(&g_cur[d], 1);
    g_csr[pos] = make_int2(s, __float_as_int(nrm));
}

// h1 = x @ W1  (100000x128 @ 128x64). 4x4 register blocking:
// 256 threads = 16 rowgrps x 16 colgrps; thread owns 4 rows x 4 cols.
// Per k4: 4 LDG.128 (x) + 4 LDS.128 (w) feed 64 FFMA -> FMA-bound.
// Weight smem swizzled by colgrp: slot k4 ^ (colgrp&7); lanes 0..7 of each
// LDS phase have distinct colgrp&7 -> conflict-free.
#define G1_TILE 64
__global__ void k_gemm1(const float* __restrict__ x, const float* __restrict__ W1) {
    __shared__ float sWt[EMB * IN_DIM];  // 32 KB, swizzled float4 layout
    for (int i = threadIdx.x; i < IN_DIM * EMB; i += blockDim.x) {
        int k = i >> 6, c = i & 63;      // W1 is [128,64] row-major
        int k4 = k >> 2, j = k & 3;
        int cg = c >> 2;
        sWt[(c * 32 + (k4 ^ (cg & 7))) * 4 + j] = W1[i];
    }
    __syncthreads();
    int rowgrp = threadIdx.x >> 4;        // 0..15
    int colgrp = threadIdx.x & 15;        // 0..15
    int sw     = colgrp & 7;
    int c0     = colgrp * 4;
    int row0   = blockIdx.x * G1_TILE + rowgrp * 4;
    // clamped row indices for reads (duplicates harmless; writes guarded)
    int r0 = min(row0 + 0, N_NODES - 1);
    int r1 = min(row0 + 1, N_NODES - 1);
    int r2 = min(row0 + 2, N_NODES - 1);
    int r3 = min(row0 + 3, N_NODES - 1);
    const float4* x0 = (const float4*)(x + (size_t)r0 * IN_DIM);
    const float4* x1 = (const float4*)(x + (size_t)r1 * IN_DIM);
    const float4* x2 = (const float4*)(x + (size_t)r2 * IN_DIM);
    const float4* x3 = (const float4*)(x + (size_t)r3 * IN_DIM);
    const float4* w0 = (const float4*)&sWt[(c0 + 0) * IN_DIM];
    const float4* w1 = (const float4*)&sWt[(c0 + 1) * IN_DIM];
    const float4* w2 = (const float4*)&sWt[(c0 + 2) * IN_DIM];
    const float4* w3 = (const float4*)&sWt[(c0 + 3) * IN_DIM];
    float acc[4][4];
#pragma unroll
    for (int r = 0; r < 4; ++r)
#pragma unroll
        for (int cc = 0; cc < 4; ++cc) acc[r][cc] = 0.f;
#pragma unroll 4
    for (int k4 = 0; k4 < IN_DIM / 4; ++k4) {
        float4 v0 = x0[k4], v1 = x1[k4], v2 = x2[k4], v3 = x3[k4];
        int ks = k4 ^ sw;
        float4 wa = w0[ks], wb = w1[ks], wc = w2[ks], wd = w3[ks];
#define DOT4(a, b) (a.x * b.x + a.y * b.y + a.z * b.z + a.w * b.w)
        acc[0][0] += DOT4(v0, wa); acc[0][1] += DOT4(v0, wb);
        acc[0][2] += DOT4(v0, wc); acc[0][3] += DOT4(v0, wd);
        acc[1][0] += DOT4(v1, wa); acc[1][1] += DOT4(v1, wb);
        acc[1][2] += DOT4(v1, wc); acc[1][3] += DOT4(v1, wd);
        acc[2][0] += DOT4(v2, wa); acc[2][1] += DOT4(v2, wb);
        acc[2][2] += DOT4(v2, wc); acc[2][3] += DOT4(v2, wd);
        acc[3][0] += DOT4(v3, wa); acc[3][1] += DOT4(v3, wb);
        acc[3][2] += DOT4(v3, wc); acc[3][3] += DOT4(v3, wd);
#undef DOT4
    }
#pragma unroll
    for (int r = 0; r < 4; ++r) {
        int row = row0 + r;
        if (row < N_NODES) {
            float4 o = make_float4(acc[r][0], acc[r][1], acc[r][2], acc[r][3]);
            *(float4*)&g_h1[(size_t)row * EMB + c0] = o;
        }
    }
}

// layer-1 aggregation: WARP PER NODE, float2 per lane.
// Meta fetched 2 edges at a time via warp-uniform int4 __ldg (broadcast):
// ~1.5 LDG warp-instrs per edge. Fused +b1, relu.
__global__ void k_agg1(const float* __restrict__ b1) {
    int node = blockIdx.x * 8 + (threadIdx.x >> 5);
    int lane = threadIdx.x & 31;
    if (node >= N_NODES) return;
    float dn = g_dis[node];
    float2 h0 = __ldg((const float2*)&g_h1[(size_t)node * EMB] + lane);
    float ax = h0.x * dn * dn, ay = h0.y * dn * dn;   // self loop
    float bx = 0.f, by = 0.f;
    int beg = g_rowp[node];
    int cnt = g_cnt [node];
    int i = 0;
    if ((beg & 1) && cnt > 0) {            // align to int4
        int2 m = __ldg(g_csr + beg);
        float w = __int_as_float(m.y);
        float2 h = __ldg((const float2*)&g_h1[(size_t)m.x * EMB] + lane);
        ax += w * h.x; ay += w * h.y;
        i = 1;
    }
    int rem   = cnt - i;
    int pairs = rem >> 1;
    const int4* p4 = (const int4*)(g_csr + beg + i);
    int j = 0;
    for (; j + 2 <= pairs; j += 2) {
        int4 ma = __ldg(p4 + j);           // 2 edges, warp-uniform -> broadcast
        int4 mb = __ldg(p4 + j + 1);
        float wa0 = __int_as_float(ma.y), wa1 = __int_as_float(ma.w);
        float wb0 = __int_as_float(mb.y), wb1 = __int_as_float(mb.w);
        float2 ha0 = __ldg((const float2*)&g_h1[(size_t)ma.x * EMB] + lane);
        float2 ha1 = __ldg((const float2*)&g_h1[(size_t)ma.z * EMB] + lane);
        float2 hb0 = __ldg((const float2*)&g_h1[(size_t)mb.x * EMB] + lane);
        float2 hb1 = __ldg((const float2*)&g_h1[(size_t)mb.z * EMB] + lane);
        ax += wa0 * ha0.x; ay += wa0 * ha0.y;
        bx += wa1 * ha1.x; by += wa1 * ha1.y;
        ax += wb0 * hb0.x; ay += wb0 * hb0.y;
        bx += wb1 * hb1.x; by += wb1 * hb1.y;
    }
    if (j < pairs) {
        int4 ma = __ldg(p4 + j);
        float wa0 = __int_as_float(ma.y), wa1 = __int_as_float(ma.w);
        float2 ha0 = __ldg((const float2*)&g_h1[(size_t)ma.x * EMB] + lane);
        float2 ha1 = __ldg((const float2*)&g_h1[(size_t)ma.z * EMB] + lane);
        ax += wa0 * ha0.x; ay += wa0 * ha0.y;
        bx += wa1 * ha1.x; by += wa1 * ha1.y;
    }
    if (rem & 1) {                          // tail edge
        int2 m = __ldg(g_csr + beg + cnt - 1);
        float w = __int_as_float(m.y);
        float2 h = __ldg((const float2*)&g_h1[(size_t)m.x * EMB] + lane);
        ax += w * h.x; ay += w * h.y;
    }
    float2 bb = __ldg((const float2*)b1 + lane);
    float2 o;
    o.x = fmaxf(ax + bx + bb.x, 0.f);
    o.y = fmaxf(ay + by + bb.y, 0.f);
    ((float2*)&g_r1[(size_t)node * EMB])[lane] = o;
}

// h2 = r1 @ W2 (100000x64 @ 64x18). R4 scalar form: sW[k*NCLS+c] puts
// consecutive c in consecutive banks (conflict-free); sA reads broadcast.
__global__ void k_gemm2(const float* __restrict__ W2) {
    __shared__ float sA[16 * EMB];
    __shared__ float sW[EMB * NCLS];
    int t = threadIdx.y * NCLS + threadIdx.x;  // 0..287
    int node0 = blockIdx.x * 16;
    for (int idx = t; idx < 16 * EMB; idx += 16 * NCLS) {
        int r = idx >> 6, cc = idx & 63;
        int node = node0 + r;
        sA[idx] = (node < N_NODES) ? g_r1[(size_t)node * EMB + cc] : 0.f;
    }
    for (int idx = t; idx < EMB * NCLS; idx += 16 * NCLS) sW[idx] = W2[idx];
    __syncthreads();
    int c    = threadIdx.x;        // 0..17
    int node = node0 + threadIdx.y;
    if (node >= N_NODES) return;
    float acc = 0.f;
#pragma unroll
    for (int k = 0; k < EMB; ++k) acc += sA[threadIdx.y * EMB + k] * sW[k * NCLS + c];
    g_h2[(size_t)node * NCLS + c] = acc;
}

// layer-2 aggregation fused with +b2 and log_softmax. Warp per node,
// int4 meta (2 edges per warp-uniform LDG).
__global__ void k_agg2_final(const float* __restrict__ b2, float* __restrict__ out,
                             int write_logits) {
    int node = blockIdx.x * 8 + (threadIdx.x >> 5);
    int lane = threadIdx.x & 31;
    if (node >= N_NODES) return;
    bool act = lane < NCLS;
    float dn  = g_dis[node];
    float acc = act ? g_h2[(size_t)node * NCLS + lane] * dn * dn : 0.f;
    float acc2 = 0.f;
    int beg = g_rowp[node];
    int cnt = g_cnt [node];
    int i = 0;
    if ((beg & 1) && cnt > 0) {
        int2 m = __ldg(g_csr + beg);
        if (act) acc += __int_as_float(m.y) * __ldg(&g_h2[(size_t)m.x * NCLS + lane]);
        i = 1;
    }
    int rem   = cnt - i;
    int pairs = rem >> 1;
    const int4* p4 = (const int4*)(g_csr + beg + i);
    for (int j = 0; j < pairs; ++j) {
        int4 ma = __ldg(p4 + j);
        if (act) {
            acc  += __int_as_float(ma.y) * __ldg(&g_h2[(size_t)ma.x * NCLS + lane]);
            acc2 += __int_as_float(ma.w) * __ldg(&g_h2[(size_t)ma.z * NCLS + lane]);
        }
    }
    if (rem & 1) {
        int2 m = __ldg(g_csr + beg + cnt - 1);
        if (act) acc += __int_as_float(m.y) * __ldg(&g_h2[(size_t)m.x * NCLS + lane]);
    }
    float v = acc + acc2 + (act ? b2[lane] : 0.f);
    float mx = act ? v : -1e30f;
#pragma unroll
    for (int off = 16; off >= 1; off >>= 1)
        mx = fmaxf(mx, __shfl_xor_sync(0xffffffffu, mx, off));
    float s = act ? __expf(v - mx) : 0.f;
#pragma unroll
    for (int off = 16; off >= 1; off >>= 1)
        s += __shfl_xor_sync(0xffffffffu, s, off);
    float lse = mx + __logf(s);
    if (act) {
        out[(size_t)node * NCLS + lane] = v - lse;
        if (write_logits)
            out[(size_t)N_NODES * NCLS + (size_t)node * NCLS + lane] = v;
    }
}

// ---------------- launch -----------------------------------------------------
extern "C" void kernel_launch(void* const* d_in, const int* in_sizes, int n_in,
                              void* d_out, int out_size) {
    const float* x  = (const float*)d_in[0];
    const int*   ei = (const int*)d_in[1];     // int64 downcast to int32 by harness
    const float* W1 = (const float*)d_in[2];
    const float* b1 = (const float*)d_in[3];
    const float* W2 = (const float*)d_in[4];
    const float* b2 = (const float*)d_in[5];
    float* out = (float*)d_out;

    int E = in_sizes[1] / 2;
    if (E > MAX_E) E = MAX_E;
    int write_logits = (out_size >= 2 * N_NODES * NCLS) ? 1 : 0;

    void* cnt_ptr = nullptr;
    cudaGetSymbolAddress(&cnt_ptr, g_cnt);
    cudaMemsetAsync(cnt_ptr, 0, N_NODES * sizeof(int));   // memset node, not a launch

    k_deg <<<(E + 255) / 256, 256>>>(ei, E);
    k_scan<<<1, 1024>>>();
    k_fill<<<(E + 255) / 256, 256>>>(ei, E);

    k_gemm1<<<(N_NODES + G1_TILE - 1) / G1_TILE, 256>>>(x, W1);  // 4th launch -> profiled
    k_agg1 <<<(N_NODES + 7) / 8, 256>>>(b1);

    k_gemm2<<<(N_NODES + 15) / 16, dim3(NCLS, 16)>>>(W2);
    k_agg2_final<<<(N_NODES + 7) / 8, 256>>>(b2, out, write_logits);
}

// round 12
// speedup vs baseline: 2.0817x; 1.0223x over previous
#include <cuda_runtime.h>
#include <cstdint>

#define N_NODES 100000
#define IN_DIM  128
#define EMB     64
#define NCLS    18
#define MAX_E   3200000

// ---------------- scratch (static device globals; no allocs) ----------------
__device__ int   g_cnt [N_NODES];     // in-degree (excl self loop)
__device__ int   g_rowp[N_NODES];     // CSR row start
__device__ int   g_cur [N_NODES];     // fill cursor
__device__ float g_dis [N_NODES];     // rsqrt(deg incl self loop)
__device__ float g_h1  [N_NODES * EMB];
__device__ float g_r1  [N_NODES * EMB];   // relu(agg1 + b1)
__device__ float g_h2  [N_NODES * NCLS];
__device__ int4  g_csr4[MAX_E / 2 + 1];   // 16B-aligned backing for CSR
#define g_csr ((int2*)g_csr4)             // (src, bitcast norm), dst-sorted

// ---------------- kernels ---------------------------------------------------

// in-degree count; int4 loads = 4 edges per LDG
__global__ void k_deg(const int* __restrict__ ei, int E) {
    int t = blockIdx.x * blockDim.x + threadIdx.x;
    int e4 = t * 4;
    if (e4 + 4 <= E) {
        int4 d = __ldg((const int4*)(ei + E) + t);
        if ((unsigned)d.x < N_NODES) atomicAdd(&g_cnt[d.x], 1);
        if ((unsigned)d.y < N_NODES) atomicAdd(&g_cnt[d.y], 1);
        if ((unsigned)d.z < N_NODES) atomicAdd(&g_cnt[d.z], 1);
        if ((unsigned)d.w < N_NODES) atomicAdd(&g_cnt[d.w], 1);
    } else {
        for (int e = e4; e < E; ++e) {
            int d = __ldg(ei + E + e);
            if ((unsigned)d < N_NODES) atomicAdd(&g_cnt[d], 1);
        }
    }
}

// single-block exclusive scan over g_cnt -> g_rowp/g_cur; also g_dis
__global__ void k_scan() {
    __shared__ int ssum[1024];
    const int CH = (N_NODES + 1023) / 1024;   // 98
    int t  = threadIdx.x;
    int lo = t * CH;
    int hi = min(lo + CH, N_NODES);
    int s = 0;
    for (int i = lo; i < hi; ++i) s += g_cnt[i];
    ssum[t] = s;
    __syncthreads();
    for (int off = 1; off < 1024; off <<= 1) {
        int u = (t >= off) ? ssum[t - off] : 0;
        __syncthreads();
        ssum[t] += u;
        __syncthreads();
    }
    int run = ssum[t] - s;   // exclusive base for this thread's chunk
    for (int i = lo; i < hi; ++i) {
        int c = g_cnt[i];
        g_rowp[i] = run;
        g_cur [i] = run;
        g_dis [i] = rsqrtf((float)(c + 1));
        run += c;
    }
}

// scatter (src, norm) into dst-sorted CSR slots
__global__ void k_fill(const int* __restrict__ ei, int E) {
    int e = blockIdx.x * blockDim.x + threadIdx.x;
    if (e >= E) return;
    int s = __ldg(ei + e);
    int d = __ldg(ei + E + e);
    if ((unsigned)s >= N_NODES) s = 0;
    if ((unsigned)d >= N_NODES) d = 0;
    float nrm = g_dis[s] * g_dis[d];
    int pos = atomicAdd(&g_cur[d], 1);
    g_csr[pos] = make_int2(s, __float_as_int(nrm));
}

// h1 = x @ W1  (100000x128 @ 128x64). 4x4 register blocking (validated R11).
#define G1_TILE 64
__global__ void k_gemm1(const float* __restrict__ x, const float* __restrict__ W1) {
    __shared__ float sWt[EMB * IN_DIM];  // 32 KB, swizzled float4 layout
    for (int i = threadIdx.x; i < IN_DIM * EMB; i += blockDim.x) {
        int k = i >> 6, c = i & 63;      // W1 is [128,64] row-major
        int k4 = k >> 2, j = k & 3;
        int cg = c >> 2;
        sWt[(c * 32 + (k4 ^ (cg & 7))) * 4 + j] = W1[i];
    }
    __syncthreads();
    int rowgrp = threadIdx.x >> 4;        // 0..15
    int colgrp = threadIdx.x & 15;        // 0..15
    int sw     = colgrp & 7;
    int c0     = colgrp * 4;
    int row0   = blockIdx.x * G1_TILE + rowgrp * 4;
    int r0 = min(row0 + 0, N_NODES - 1);
    int r1 = min(row0 + 1, N_NODES - 1);
    int r2 = min(row0 + 2, N_NODES - 1);
    int r3 = min(row0 + 3, N_NODES - 1);
    const float4* x0 = (const float4*)(x + (size_t)r0 * IN_DIM);
    const float4* x1 = (const float4*)(x + (size_t)r1 * IN_DIM);
    const float4* x2 = (const float4*)(x + (size_t)r2 * IN_DIM);
    const float4* x3 = (const float4*)(x + (size_t)r3 * IN_DIM);
    const float4* w0 = (const float4*)&sWt[(c0 + 0) * IN_DIM];
    const float4* w1 = (const float4*)&sWt[(c0 + 1) * IN_DIM];
    const float4* w2 = (const float4*)&sWt[(c0 + 2) * IN_DIM];
    const float4* w3 = (const float4*)&sWt[(c0 + 3) * IN_DIM];
    float acc[4][4];
#pragma unroll
    for (int r = 0; r < 4; ++r)
#pragma unroll
        for (int cc = 0; cc < 4; ++cc) acc[r][cc] = 0.f;
#pragma unroll 4
    for (int k4 = 0; k4 < IN_DIM / 4; ++k4) {
        float4 v0 = x0[k4], v1 = x1[k4], v2 = x2[k4], v3 = x3[k4];
        int ks = k4 ^ sw;
        float4 wa = w0[ks], wb = w1[ks], wc = w2[ks], wd = w3[ks];
#define DOT4(a, b) (a.x * b.x + a.y * b.y + a.z * b.z + a.w * b.w)
        acc[0][0] += DOT4(v0, wa); acc[0][1] += DOT4(v0, wb);
        acc[0][2] += DOT4(v0, wc); acc[0][3] += DOT4(v0, wd);
        acc[1][0] += DOT4(v1, wa); acc[1][1] += DOT4(v1, wb);
        acc[1][2] += DOT4(v1, wc); acc[1][3] += DOT4(v1, wd);
        acc[2][0] += DOT4(v2, wa); acc[2][1] += DOT4(v2, wb);
        acc[2][2] += DOT4(v2, wc); acc[2][3] += DOT4(v2, wd);
        acc[3][0] += DOT4(v3, wa); acc[3][1] += DOT4(v3, wb);
        acc[3][2] += DOT4(v3, wc); acc[3][3] += DOT4(v3, wd);
#undef DOT4
    }
#pragma unroll
    for (int r = 0; r < 4; ++r) {
        int row = row0 + r;
        if (row < N_NODES) {
            float4 o = make_float4(acc[r][0], acc[r][1], acc[r][2], acc[r][3]);
            *(float4*)&g_h1[(size_t)row * EMB + c0] = o;
        }
    }
}

// layer-1 aggregation: WARP PER NODE; 16 lanes x float4 per edge, two edges
// per gather instruction (half = lane>>4 picks the edge from a warp-uniform
// int4 meta). 1 meta LDG + 1 gather LDG per edge pair (~1.0 LDG/edge).
// Halves combined via 4 shfl at the end. Fused +b1, relu.
__global__ void k_agg1(const float* __restrict__ b1) {
    int node = blockIdx.x * 8 + (threadIdx.x >> 5);
    int lane = threadIdx.x & 31;
    if (node >= N_NODES) return;
    int half = lane >> 4;   // 0: even edge of pair, 1: odd edge
    int q    = lane & 15;   // float4 column chunk
    float dn = g_dis[node];
    float4 acc = make_float4(0.f, 0.f, 0.f, 0.f);
    float4 acc2 = make_float4(0.f, 0.f, 0.f, 0.f);
    if (half == 0) {        // self loop counted once
        float4 h = __ldg((const float4*)&g_h1[(size_t)node * EMB] + q);
        float s2 = dn * dn;
        acc.x = h.x * s2; acc.y = h.y * s2; acc.z = h.z * s2; acc.w = h.w * s2;
    }
    int beg = g_rowp[node];
    int cnt = g_cnt [node];
    int i = 0;
    if ((beg & 1) && cnt > 0) {            // align to int4
        if (half == 0) {
            int2 m = __ldg(g_csr + beg);
            float w = __int_as_float(m.y);
            float4 h = __ldg((const float4*)&g_h1[(size_t)m.x * EMB] + q);
            acc.x += w * h.x; acc.y += w * h.y; acc.z += w * h.z; acc.w += w * h.w;
        }
        i = 1;
    }
    int rem   = cnt - i;
    int pairs = rem >> 1;
    const int4* p4 = (const int4*)(g_csr + beg + i);
    int j = 0;
    for (; j + 2 <= pairs; j += 2) {
        int4 m0 = __ldg(p4 + j);
        int4 m1 = __ldg(p4 + j + 1);
        int   s0 = half ? m0.z : m0.x;
        int   s1 = half ? m1.z : m1.x;
        float w0 = __int_as_float(half ? m0.w : m0.y);
        float w1 = __int_as_float(half ? m1.w : m1.y);
        float4 h0 = __ldg((const float4*)&g_h1[(size_t)s0 * EMB] + q);
        float4 h1 = __ldg((const float4*)&g_h1[(size_t)s1 * EMB] + q);
        acc.x  += w0 * h0.x; acc.y  += w0 * h0.y; acc.z  += w0 * h0.z; acc.w  += w0 * h0.w;
        acc2.x += w1 * h1.x; acc2.y += w1 * h1.y; acc2.z += w1 * h1.z; acc2.w += w1 * h1.w;
    }
    if (j < pairs) {
        int4 m0 = __ldg(p4 + j);
        int   s0 = half ? m0.z : m0.x;
        float w0 = __int_as_float(half ? m0.w : m0.y);
        float4 h0 = __ldg((const float4*)&g_h1[(size_t)s0 * EMB] + q);
        acc.x += w0 * h0.x; acc.y += w0 * h0.y; acc.z += w0 * h0.z; acc.w += w0 * h0.w;
    }
    if (rem & 1) {                          // tail edge
        if (half == 0) {
            int2 m = __ldg(g_csr + beg + cnt - 1);
            float w = __int_as_float(m.y);
            float4 h = __ldg((const float4*)&g_h1[(size_t)m.x * EMB] + q);
            acc.x += w * h.x; acc.y += w * h.y; acc.z += w * h.z; acc.w += w * h.w;
        }
    }
    acc.x += acc2.x; acc.y += acc2.y; acc.z += acc2.z; acc.w += acc2.w;
    // combine the two halves (lanes j and j^16 hold same columns)
    acc.x += __shfl_xor_sync(0xffffffffu, acc.x, 16);
    acc.y += __shfl_xor_sync(0xffffffffu, acc.y, 16);
    acc.z += __shfl_xor_sync(0xffffffffu, acc.z, 16);
    acc.w += __shfl_xor_sync(0xffffffffu, acc.w, 16);
    if (half == 0) {
        float4 bb = __ldg((const float4*)b1 + q);
        float4 o;
        o.x = fmaxf(acc.x + bb.x, 0.f);
        o.y = fmaxf(acc.y + bb.y, 0.f);
        o.z = fmaxf(acc.z + bb.z, 0.f);
        o.w = fmaxf(acc.w + bb.w, 0.f);
        ((float4*)&g_r1[(size_t)node * EMB])[q] = o;
    }
}

// h2 = r1 @ W2 (100000x64 @ 64x18). R4 scalar form (conflict-free).
__global__ void k_gemm2(const float* __restrict__ W2) {
    __shared__ float sA[16 * EMB];
    __shared__ float sW[EMB * NCLS];
    int t = threadIdx.y * NCLS + threadIdx.x;  // 0..287
    int node0 = blockIdx.x * 16;
    for (int idx = t; idx < 16 * EMB; idx += 16 * NCLS) {
        int r = idx >> 6, cc = idx & 63;
        int node = node0 + r;
        sA[idx] = (node < N_NODES) ? g_r1[(size_t)node * EMB + cc] : 0.f;
    }
    for (int idx = t; idx < EMB * NCLS; idx += 16 * NCLS) sW[idx] = W2[idx];
    __syncthreads();
    int c    = threadIdx.x;        // 0..17
    int node = node0 + threadIdx.y;
    if (node >= N_NODES) return;
    float acc = 0.f;
#pragma unroll
    for (int k = 0; k < EMB; ++k) acc += sA[threadIdx.y * EMB + k] * sW[k * NCLS + c];
    g_h2[(size_t)node * NCLS + c] = acc;
}

// layer-2 aggregation fused with +b2 and log_softmax. Warp per node,
// int4 meta (2 edges per warp-uniform LDG).
__global__ void k_agg2_final(const float* __restrict__ b2, float* __restrict__ out,
                             int write_logits) {
    int node = blockIdx.x * 8 + (threadIdx.x >> 5);
    int lane = threadIdx.x & 31;
    if (node >= N_NODES) return;
    bool act = lane < NCLS;
    float dn  = g_dis[node];
    float acc = act ? g_h2[(size_t)node * NCLS + lane] * dn * dn : 0.f;
    float acc2 = 0.f;
    int beg = g_rowp[node];
    int cnt = g_cnt [node];
    int i = 0;
    if ((beg & 1) && cnt > 0) {
        int2 m = __ldg(g_csr + beg);
        if (act) acc += __int_as_float(m.y) * __ldg(&g_h2[(size_t)m.x * NCLS + lane]);
        i = 1;
    }
    int rem   = cnt - i;
    int pairs = rem >> 1;
    const int4* p4 = (const int4*)(g_csr + beg + i);
    for (int j = 0; j < pairs; ++j) {
        int4 ma = __ldg(p4 + j);
        if (act) {
            acc  += __int_as_float(ma.y) * __ldg(&g_h2[(size_t)ma.x * NCLS + lane]);
            acc2 += __int_as_float(ma.w) * __ldg(&g_h2[(size_t)ma.z * NCLS + lane]);
        }
    }
    if (rem & 1) {
        int2 m = __ldg(g_csr + beg + cnt - 1);
        if (act) acc += __int_as_float(m.y) * __ldg(&g_h2[(size_t)m.x * NCLS + lane]);
    }
    float v = acc + acc2 + (act ? b2[lane] : 0.f);
    float mx = act ? v : -1e30f;
#pragma unroll
    for (int off = 16; off >= 1; off >>= 1)
        mx = fmaxf(mx, __shfl_xor_sync(0xffffffffu, mx, off));
    float s = act ? __expf(v - mx) : 0.f;
#pragma unroll
    for (int off = 16; off >= 1; off >>= 1)
        s += __shfl_xor_sync(0xffffffffu, s, off);
    float lse = mx + __logf(s);
    if (act) {
        out[(size_t)node * NCLS + lane] = v - lse;
        if (write_logits)
            out[(size_t)N_NODES * NCLS + (size_t)node * NCLS + lane] = v;
    }
}

// ---------------- launch -----------------------------------------------------
extern "C" void kernel_launch(void* const* d_in, const int* in_sizes, int n_in,
                              void* d_out, int out_size) {
    const float* x  = (const float*)d_in[0];
    const int*   ei = (const int*)d_in[1];     // int64 downcast to int32 by harness
    const float* W1 = (const float*)d_in[2];
    const float* b1 = (const float*)d_in[3];
    const float* W2 = (const float*)d_in[4];
    const float* b2 = (const float*)d_in[5];
    float* out = (float*)d_out;

    int E = in_sizes[1] / 2;
    if (E > MAX_E) E = MAX_E;
    int write_logits = (out_size >= 2 * N_NODES * NCLS) ? 1 : 0;

    // lazy side-stream + events (host-side infra; device work per call unchanged)
    static cudaStream_t s1 = nullptr;
    static cudaEvent_t  ev0 = nullptr, ev1 = nullptr;
    static int init_done = 0;
    if (!init_done) {
        init_done = 1;
        if (cudaStreamCreateWithFlags(&s1, cudaStreamNonBlocking) != cudaSuccess) s1 = nullptr;
        if (s1) {
            if (cudaEventCreateWithFlags(&ev0, cudaEventDisableTiming) != cudaSuccess ||
                cudaEventCreateWithFlags(&ev1, cudaEventDisableTiming) != cudaSuccess) {
                s1 = nullptr;
            }
        }
    }

    void* cnt_ptr = nullptr;
    cudaGetSymbolAddress(&cnt_ptr, g_cnt);
    cudaMemsetAsync(cnt_ptr, 0, N_NODES * sizeof(int));

    int nE4 = (E + 1023) / 1024;  // 4 edges per thread, 256 threads/block

    if (s1) {
        // fork: gemm1 (independent) runs parallel to the CSR build chain
        cudaEventRecord(ev0, 0);
        cudaStreamWaitEvent(s1, ev0, 0);
        k_gemm1<<<(N_NODES + G1_TILE - 1) / G1_TILE, 256, 0, s1>>>(x, W1);
        cudaEventRecord(ev1, s1);

        k_deg <<<nE4, 256>>>(ei, E);
        k_scan<<<1, 1024>>>();
        k_fill<<<(E + 255) / 256, 256>>>(ei, E);

        cudaStreamWaitEvent(0, ev1, 0);    // join before agg1
    } else {
        k_deg <<<nE4, 256>>>(ei, E);
        k_scan<<<1, 1024>>>();
        k_fill<<<(E + 255) / 256, 256>>>(ei, E);
        k_gemm1<<<(N_NODES + G1_TILE - 1) / G1_TILE, 256>>>(x, W1);
    }

    k_agg1 <<<(N_NODES + 7) / 8, 256>>>(b1);
    k_gemm2<<<(N_NODES + 15) / 16, dim3(NCLS, 16)>>>(W2);
    k_agg2_final<<<(N_NODES + 7) / 8, 256>>>(b2, out, write_logits);
}

// round 14
// speedup vs baseline: 3.4694x; 1.6667x over previous
#include <cuda_runtime.h>
#include <cstdint>

#define N_NODES 100000
#define IN_DIM  128
#define EMB     64
#define NCLS    18
#define MAX_E   3200000
#define NCHUNK  512
#define NBLK    ((N_NODES + NCHUNK - 1) / NCHUNK)   // 196

// ---------------- scratch (static device globals; no allocs) ----------------
__device__ int   g_cnt [N_NODES];     // in-degree (excl self loop)
__device__ int   g_rowp[N_NODES];     // CSR row start
__device__ int   g_cur [N_NODES];     // fill cursor
__device__ float g_dis [N_NODES];     // rsqrt(deg incl self loop)
__device__ int   g_part[NBLK];        // per-chunk partial sums
__device__ float g_h1  [N_NODES * EMB];
__device__ float g_r1  [N_NODES * EMB];   // relu(agg1 + b1)
__device__ float g_h2  [N_NODES * NCLS];
__device__ int4  g_csr4[MAX_E / 2 + 1];   // 16B-aligned backing for CSR
#define g_csr ((int2*)g_csr4)             // (src, bitcast norm), dst-sorted

// ---------------- kernels ---------------------------------------------------

// in-degree count; int4 loads = 4 edges per LDG
__global__ void k_deg(const int* __restrict__ ei, int E) {
    int t = blockIdx.x * blockDim.x + threadIdx.x;
    int e4 = t * 4;
    if (e4 + 4 <= E) {
        int4 d = __ldg((const int4*)(ei + E) + t);
        if ((unsigned)d.x < N_NODES) atomicAdd(&g_cnt[d.x], 1);
        if ((unsigned)d.y < N_NODES) atomicAdd(&g_cnt[d.y], 1);
        if ((unsigned)d.z < N_NODES) atomicAdd(&g_cnt[d.z], 1);
        if ((unsigned)d.w < N_NODES) atomicAdd(&g_cnt[d.w], 1);
    } else {
        for (int e = e4; e < E; ++e) {
            int d = __ldg(ei + E + e);
            if ((unsigned)d < N_NODES) atomicAdd(&g_cnt[d], 1);
        }
    }
}

// parallel scan stage A: coalesced per-chunk partial sums
__global__ void k_scanA() {
    __shared__ int sred[NCHUNK];
    int b = blockIdx.x;
    int i = b * NCHUNK + threadIdx.x;
    sred[threadIdx.x] = (i < N_NODES) ? g_cnt[i] : 0;
    __syncthreads();
    for (int off = NCHUNK / 2; off >= 1; off >>= 1) {
        if (threadIdx.x < off) sred[threadIdx.x] += sred[threadIdx.x + off];
        __syncthreads();
    }
    if (threadIdx.x == 0) g_part[b] = sred[0];
}

// parallel scan stage C: per-chunk inclusive scan + cross-chunk offset;
// coalesced writes of rowp/cur/dis.
__global__ void k_scanC() {
    __shared__ int s[NCHUNK];
    __shared__ int soff;
    int b = blockIdx.x;
    int t = threadIdx.x;
    int i = b * NCHUNK + t;
    int v = (i < N_NODES) ? g_cnt[i] : 0;
    s[t] = v;
    __syncthreads();
    for (int off = 1; off < NCHUNK; off <<= 1) {
        int u = (t >= off) ? s[t - off] : 0;
        __syncthreads();
        s[t] += u;
        __syncthreads();
    }
    if (t < 32) {
        int acc = 0;
        for (int j = t; j < b; j += 32) acc += g_part[j];
#pragma unroll
        for (int o = 16; o >= 1; o >>= 1) acc += __shfl_xor_sync(0xffffffffu, acc, o);
        if (t == 0) soff = acc;
    }
    __syncthreads();
    if (i < N_NODES) {
        int excl = s[t] + soff - v;
        g_rowp[i] = excl;
        g_cur [i] = excl;
        g_dis [i] = rsqrtf((float)(v + 1));
    }
}

// scatter (src, norm) into dst-sorted CSR slots
__global__ void k_fill(const int* __restrict__ ei, int E) {
    int e = blockIdx.x * blockDim.x + threadIdx.x;
    if (e >= E) return;
    int s = __ldg(ei + e);
    int d = __ldg(ei + E + e);
    if ((unsigned)s >= N_NODES) s = 0;
    if ((unsigned)d >= N_NODES) d = 0;
    float nrm = g_dis[s] * g_dis[d];
    int pos = atomicAdd(&g_cur[d], 1);
    g_csr[pos] = make_int2(s, __float_as_int(nrm));
}

// h1 = x @ W1  (100000x128 @ 128x64). 4x4 register blocking (validated R11).
#define G1_TILE 64
__global__ void k_gemm1(const float* __restrict__ x, const float* __restrict__ W1) {
    __shared__ float sWt[EMB * IN_DIM];  // 32 KB, swizzled float4 layout
    for (int i = threadIdx.x; i < IN_DIM * EMB; i += blockDim.x) {
        int k = i >> 6, c = i & 63;      // W1 is [128,64] row-major
        int k4 = k >> 2, j = k & 3;
        int cg = c >> 2;
        sWt[(c * 32 + (k4 ^ (cg & 7))) * 4 + j] = W1[i];
    }
    __syncthreads();
    int rowgrp = threadIdx.x >> 4;        // 0..15
    int colgrp = threadIdx.x & 15;        // 0..15
    int sw     = colgrp & 7;
    int c0     = colgrp * 4;
    int row0   = blockIdx.x * G1_TILE + rowgrp * 4;
    int r0 = min(row0 + 0, N_NODES - 1);
    int r1 = min(row0 + 1, N_NODES - 1);
    int r2 = min(row0 + 2, N_NODES - 1);
    int r3 = min(row0 + 3, N_NODES - 1);
    const float4* x0 = (const float4*)(x + (size_t)r0 * IN_DIM);
    const float4* x1 = (const float4*)(x + (size_t)r1 * IN_DIM);
    const float4* x2 = (const float4*)(x + (size_t)r2 * IN_DIM);
    const float4* x3 = (const float4*)(x + (size_t)r3 * IN_DIM);
    const float4* w0 = (const float4*)&sWt[(c0 + 0) * IN_DIM];
    const float4* w1 = (const float4*)&sWt[(c0 + 1) * IN_DIM];
    const float4* w2 = (const float4*)&sWt[(c0 + 2) * IN_DIM];
    const float4* w3 = (const float4*)&sWt[(c0 + 3) * IN_DIM];
    float acc[4][4];
#pragma unroll
    for (int r = 0; r < 4; ++r)
#pragma unroll
        for (int cc = 0; cc < 4; ++cc) acc[r][cc] = 0.f;
#pragma unroll 4
    for (int k4 = 0; k4 < IN_DIM / 4; ++k4) {
        float4 v0 = x0[k4], v1 = x1[k4], v2 = x2[k4], v3 = x3[k4];
        int ks = k4 ^ sw;
        float4 wa = w0[ks], wb = w1[ks], wc = w2[ks], wd = w3[ks];
#define DOT4(a, b) (a.x * b.x + a.y * b.y + a.z * b.z + a.w * b.w)
        acc[0][0] += DOT4(v0, wa); acc[0][1] += DOT4(v0, wb);
        acc[0][2] += DOT4(v0, wc); acc[0][3] += DOT4(v0, wd);
        acc[1][0] += DOT4(v1, wa); acc[1][1] += DOT4(v1, wb);
        acc[1][2] += DOT4(v1, wc); acc[1][3] += DOT4(v1, wd);
        acc[2][0] += DOT4(v2, wa); acc[2][1] += DOT4(v2, wb);
        acc[2][2] += DOT4(v2, wc); acc[2][3] += DOT4(v2, wd);
        acc[3][0] += DOT4(v3, wa); acc[3][1] += DOT4(v3, wb);
        acc[3][2] += DOT4(v3, wc); acc[3][3] += DOT4(v3, wd);
#undef DOT4
    }
#pragma unroll
    for (int r = 0; r < 4; ++r) {
        int row = row0 + r;
        if (row < N_NODES) {
            float4 o = make_float4(acc[r][0], acc[r][1], acc[r][2], acc[r][3]);
            *(float4*)&g_h1[(size_t)row * EMB + c0] = o;
        }
    }
}

// layer-1 aggregation: WARP PER NODE, float2 per lane (R11-measured best).
// int4 meta = 2 edges per warp-uniform LDG; ~1.5 LDG/edge. Fused +b1, relu.
__global__ void k_agg1(const float* __restrict__ b1) {
    int node = blockIdx.x * 8 + (threadIdx.x >> 5);
    int lane = threadIdx.x & 31;
    if (node >= N_NODES) return;
    float dn = g_dis[node];
    float2 h0 = __ldg((const float2*)&g_h1[(size_t)node * EMB] + lane);
    float ax = h0.x * dn * dn, ay = h0.y * dn * dn;   // self loop
    float bx = 0.f, by = 0.f;
    int beg = g_rowp[node];
    int cnt = g_cnt [node];
    int i = 0;
    if ((beg & 1) && cnt > 0) {            // align to int4
        int2 m = __ldg(g_csr + beg);
        float w = __int_as_float(m.y);
        float2 h = __ldg((const float2*)&g_h1[(size_t)m.x * EMB] + lane);
        ax += w * h.x; ay += w * h.y;
        i = 1;
    }
    int rem   = cnt - i;
    int pairs = rem >> 1;
    const int4* p4 = (const int4*)(g_csr + beg + i);
    int j = 0;
    for (; j + 2 <= pairs; j += 2) {
        int4 ma = __ldg(p4 + j);           // 2 edges, warp-uniform -> broadcast
        int4 mb = __ldg(p4 + j + 1);
        float wa0 = __int_as_float(ma.y), wa1 = __int_as_float(ma.w);
        float wb0 = __int_as_float(mb.y), wb1 = __int_as_float(mb.w);
        float2 ha0 = __ldg((const float2*)&g_h1[(size_t)ma.x * EMB] + lane);
        float2 ha1 = __ldg((const float2*)&g_h1[(size_t)ma.z * EMB] + lane);
        float2 hb0 = __ldg((const float2*)&g_h1[(size_t)mb.x * EMB] + lane);
        float2 hb1 = __ldg((const float2*)&g_h1[(size_t)mb.z * EMB] + lane);
        ax += wa0 * ha0.x; ay += wa0 * ha0.y;
        bx += wa1 * ha1.x; by += wa1 * ha1.y;
        ax += wb0 * hb0.x; ay += wb0 * hb0.y;
        bx += wb1 * hb1.x; by += wb1 * hb1.y;
    }
    if (j < pairs) {
        int4 ma = __ldg(p4 + j);
        float wa0 = __int_as_float(ma.y), wa1 = __int_as_float(ma.w);
        float2 ha0 = __ldg((const float2*)&g_h1[(size_t)ma.x * EMB] + lane);
        float2 ha1 = __ldg((const float2*)&g_h1[(size_t)ma.z * EMB] + lane);
        ax += wa0 * ha0.x; ay += wa0 * ha0.y;
        bx += wa1 * ha1.x; by += wa1 * ha1.y;
    }
    if (rem & 1) {                          // tail edge
        int2 m = __ldg(g_csr + beg + cnt - 1);
        float w = __int_as_float(m.y);
        float2 h = __ldg((const float2*)&g_h1[(size_t)m.x * EMB] + lane);
        ax += w * h.x; ay += w * h.y;
    }
    float2 bb = __ldg((const float2*)b1 + lane);
    float2 o;
    o.x = fmaxf(ax + bx + bb.x, 0.f);
    o.y = fmaxf(ay + by + bb.y, 0.f);
    ((float2*)&g_r1[(size_t)node * EMB])[lane] = o;
}

// h2 = r1 @ W2 (100000x64 @ 64x18). R4 scalar form (conflict-free).
__global__ void k_gemm2(const float* __restrict__ W2) {
    __shared__ float sA[16 * EMB];
    __shared__ float sW[EMB * NCLS];
    int t = threadIdx.y * NCLS + threadIdx.x;  // 0..287
    int node0 = blockIdx.x * 16;
    for (int idx = t; idx < 16 * EMB; idx += 16 * NCLS) {
        int r = idx >> 6, cc = idx & 63;
        int node = node0 + r;
        sA[idx] = (node < N_NODES) ? g_r1[(size_t)node * EMB + cc] : 0.f;
    }
    for (int idx = t; idx < EMB * NCLS; idx += 16 * NCLS) sW[idx] = W2[idx];
    __syncthreads();
    int c    = threadIdx.x;        // 0..17
    int node = node0 + threadIdx.y;
    if (node >= N_NODES) return;
    float acc = 0.f;
#pragma unroll
    for (int k = 0; k < EMB; ++k) acc += sA[threadIdx.y * EMB + k] * sW[k * NCLS + c];
    g_h2[(size_t)node * NCLS + c] = acc;
}

// layer-2 aggregation fused with +b2 and log_softmax. Warp per node,
// int4 meta (2 edges per warp-uniform LDG).
__global__ void k_agg2_final(const float* __restrict__ b2, float* __restrict__ out,
                             int write_logits) {
    int node = blockIdx.x * 8 + (threadIdx.x >> 5);
    int lane = threadIdx.x & 31;
    if (node >= N_NODES) return;
    bool act = lane < NCLS;
    float dn  = g_dis[node];
    float acc = act ? g_h2[(size_t)node * NCLS + lane] * dn * dn : 0.f;
    float acc2 = 0.f;
    int beg = g_rowp[node];
    int cnt = g_cnt [node];
    int i = 0;
    if ((beg & 1) && cnt > 0) {
        int2 m = __ldg(g_csr + beg);
        if (act) acc += __int_as_float(m.y) * __ldg(&g_h2[(size_t)m.x * NCLS + lane]);
        i = 1;
    }
    int rem   = cnt - i;
    int pairs = rem >> 1;
    const int4* p4 = (const int4*)(g_csr + beg + i);
    for (int j = 0; j < pairs; ++j) {
        int4 ma = __ldg(p4 + j);
        if (act) {
            acc  += __int_as_float(ma.y) * __ldg(&g_h2[(size_t)ma.x * NCLS + lane]);
            acc2 += __int_as_float(ma.w) * __ldg(&g_h2[(size_t)ma.z * NCLS + lane]);
        }
    }
    if (rem & 1) {
        int2 m = __ldg(g_csr + beg + cnt - 1);
        if (act) acc += __int_as_float(m.y) * __ldg(&g_h2[(size_t)m.x * NCLS + lane]);
    }
    float v = acc + acc2 + (act ? b2[lane] : 0.f);
    float mx = act ? v : -1e30f;
#pragma unroll
    for (int off = 16; off >= 1; off >>= 1)
        mx = fmaxf(mx, __shfl_xor_sync(0xffffffffu, mx, off));
    float s = act ? __expf(v - mx) : 0.f;
#pragma unroll
    for (int off = 16; off >= 1; off >>= 1)
        s += __shfl_xor_sync(0xffffffffu, s, off);
    float lse = mx + __logf(s);
    if (act) {
        out[(size_t)node * NCLS + lane] = v - lse;
        if (write_logits)
            out[(size_t)N_NODES * NCLS + (size_t)node * NCLS + lane] = v;
    }
}

// ---------------- launch -----------------------------------------------------
extern "C" void kernel_launch(void* const* d_in, const int* in_sizes, int n_in,
                              void* d_out, int out_size) {
    const float* x  = (const float*)d_in[0];
    const int*   ei = (const int*)d_in[1];     // int64 downcast to int32 by harness
    const float* W1 = (const float*)d_in[2];
    const float* b1 = (const float*)d_in[3];
    const float* W2 = (const float*)d_in[4];
    const float* b2 = (const float*)d_in[5];
    float* out = (float*)d_out;

    int E = in_sizes[1] / 2;
    if (E > MAX_E) E = MAX_E;
    int write_logits = (out_size >= 2 * N_NODES * NCLS) ? 1 : 0;

    // lazy side-stream + events (host-side infra; device work per call unchanged)
    static cudaStream_t s1 = nullptr;
    static cudaEvent_t  ev0 = nullptr, ev1 = nullptr;
    static int init_done = 0;
    if (!init_done) {
        init_done = 1;
        if (cudaStreamCreateWithFlags(&s1, cudaStreamNonBlocking) != cudaSuccess) s1 = nullptr;
        if (s1) {
            if (cudaEventCreateWithFlags(&ev0, cudaEventDisableTiming) != cudaSuccess ||
                cudaEventCreateWithFlags(&ev1, cudaEventDisableTiming) != cudaSuccess) {
                s1 = nullptr;
            }
        }
    }

    void* cnt_ptr = nullptr;
    cudaGetSymbolAddress(&cnt_ptr, g_cnt);
    cudaMemsetAsync(cnt_ptr, 0, N_NODES * sizeof(int));

    int nE4 = (E + 1023) / 1024;  // 4 edges per thread, 256 threads/block

    if (s1) {
        // fork: gemm1 (independent) runs parallel to the CSR build chain
        cudaEventRecord(ev0, 0);
        cudaStreamWaitEvent(s1, ev0, 0);
        k_gemm1<<<(N_NODES + G1_TILE - 1) / G1_TILE, 256, 0, s1>>>(x, W1);
        cudaEventRecord(ev1, s1);

        k_deg  <<<nE4, 256>>>(ei, E);
        k_scanA<<<NBLK, NCHUNK>>>();
        k_scanC<<<NBLK, NCHUNK>>>();       // 4th kernel launch -> profiled
        k_fill <<<(E + 255) / 256, 256>>>(ei, E);

        cudaStreamWaitEvent(0, ev1, 0);    // join before agg1
    } else {
        k_deg  <<<nE4, 256>>>(ei, E);
        k_scanA<<<NBLK, NCHUNK>>>();
        k_scanC<<<NBLK, NCHUNK>>>();
        k_fill <<<(E + 255) / 256, 256>>>(ei, E);
        k_gemm1<<<(N_NODES + G1_TILE - 1) / G1_TILE, 256>>>(x, W1);
    }

    k_agg1 <<<(N_NODES + 7) / 8, 256>>>(b1);
    k_gemm2<<<(N_NODES + 15) / 16, dim3(NCLS, 16)>>>(W2);
    k_agg2_final<<<(N_NODES + 7) / 8, 256>>>(b2, out, write_logits);
}

// round 16
// speedup vs baseline: 3.6623x; 1.0556x over previous
#include <cuda_runtime.h>
#include <cstdint>

#define N_NODES 100000
#define IN_DIM  128
#define EMB     64
#define NCLS    18
#define MAX_E   3200000
#define NCHUNK  512
#define NBLK    ((N_NODES + NCHUNK - 1) / NCHUNK)   // 196

// ---------------- scratch (static device globals; no allocs) ----------------
__device__ int   g_cnt [N_NODES];     // in-degree (excl self loop)
__device__ int   g_rowp[N_NODES];     // CSR row start
__device__ int   g_cur [N_NODES];     // fill cursor
__device__ float g_dis [N_NODES];     // rsqrt(deg incl self loop)
__device__ int   g_part[NBLK];        // per-chunk partial sums
__device__ float g_h1  [N_NODES * EMB];
__device__ float g_h2  [N_NODES * NCLS];
__device__ int4  g_csr4[MAX_E / 2 + 1];   // 16B-aligned backing for CSR
#define g_csr ((int2*)g_csr4)             // (src, bitcast norm), dst-sorted

// ---------------- kernels ---------------------------------------------------

// in-degree count; int4 loads = 4 edges per LDG
__global__ void k_deg(const int* __restrict__ ei, int E) {
    int t = blockIdx.x * blockDim.x + threadIdx.x;
    int e4 = t * 4;
    if (e4 + 4 <= E) {
        int4 d = __ldg((const int4*)(ei + E) + t);
        if ((unsigned)d.x < N_NODES) atomicAdd(&g_cnt[d.x], 1);
        if ((unsigned)d.y < N_NODES) atomicAdd(&g_cnt[d.y], 1);
        if ((unsigned)d.z < N_NODES) atomicAdd(&g_cnt[d.z], 1);
        if ((unsigned)d.w < N_NODES) atomicAdd(&g_cnt[d.w], 1);
    } else {
        for (int e = e4; e < E; ++e) {
            int d = __ldg(ei + E + e);
            if ((unsigned)d < N_NODES) atomicAdd(&g_cnt[d], 1);
        }
    }
}

// parallel scan stage A: coalesced per-chunk partial sums
__global__ void k_scanA() {
    __shared__ int sred[NCHUNK];
    int b = blockIdx.x;
    int i = b * NCHUNK + threadIdx.x;
    sred[threadIdx.x] = (i < N_NODES) ? g_cnt[i] : 0;
    __syncthreads();
    for (int off = NCHUNK / 2; off >= 1; off >>= 1) {
        if (threadIdx.x < off) sred[threadIdx.x] += sred[threadIdx.x + off];
        __syncthreads();
    }
    if (threadIdx.x == 0) g_part[b] = sred[0];
}

// parallel scan stage C: per-chunk inclusive scan + cross-chunk offset;
// coalesced writes of rowp/cur/dis.
__global__ void k_scanC() {
    __shared__ int s[NCHUNK];
    __shared__ int soff;
    int b = blockIdx.x;
    int t = threadIdx.x;
    int i = b * NCHUNK + t;
    int v = (i < N_NODES) ? g_cnt[i] : 0;
    s[t] = v;
    __syncthreads();
    for (int off = 1; off < NCHUNK; off <<= 1) {
        int u = (t >= off) ? s[t - off] : 0;
        __syncthreads();
        s[t] += u;
        __syncthreads();
    }
    if (t < 32) {
        int acc = 0;
        for (int j = t; j < b; j += 32) acc += g_part[j];
#pragma unroll
        for (int o = 16; o >= 1; o >>= 1) acc += __shfl_xor_sync(0xffffffffu, acc, o);
        if (t == 0) soff = acc;
    }
    __syncthreads();
    if (i < N_NODES) {
        int excl = s[t] + soff - v;
        g_rowp[i] = excl;
        g_cur [i] = excl;
        g_dis [i] = rsqrtf((float)(v + 1));
    }
}

// scatter (src, norm) into dst-sorted CSR slots
__global__ void k_fill(const int* __restrict__ ei, int E) {
    int e = blockIdx.x * blockDim.x + threadIdx.x;
    if (e >= E) return;
    int s = __ldg(ei + e);
    int d = __ldg(ei + E + e);
    if ((unsigned)s >= N_NODES) s = 0;
    if ((unsigned)d >= N_NODES) d = 0;
    float nrm = g_dis[s] * g_dis[d];
    int pos = atomicAdd(&g_cur[d], 1);
    g_csr[pos] = make_int2(s, __float_as_int(nrm));
}

// h1 = x @ W1  (100000x128 @ 128x64). 4x4 register blocking (validated R11).
#define G1_TILE 64
__global__ void k_gemm1(const float* __restrict__ x, const float* __restrict__ W1) {
    __shared__ float sWt[EMB * IN_DIM];  // 32 KB, swizzled float4 layout
    for (int i = threadIdx.x; i < IN_DIM * EMB; i += blockDim.x) {
        int k = i >> 6, c = i & 63;      // W1 is [128,64] row-major
        int k4 = k >> 2, j = k & 3;
        int cg = c >> 2;
        sWt[(c * 32 + (k4 ^ (cg & 7))) * 4 + j] = W1[i];
    }
    __syncthreads();
    int rowgrp = threadIdx.x >> 4;        // 0..15
    int colgrp = threadIdx.x & 15;        // 0..15
    int sw     = colgrp & 7;
    int c0     = colgrp * 4;
    int row0   = blockIdx.x * G1_TILE + rowgrp * 4;
    int r0 = min(row0 + 0, N_NODES - 1);
    int r1 = min(row0 + 1, N_NODES - 1);
    int r2 = min(row0 + 2, N_NODES - 1);
    int r3 = min(row0 + 3, N_NODES - 1);
    const float4* x0 = (const float4*)(x + (size_t)r0 * IN_DIM);
    const float4* x1 = (const float4*)(x + (size_t)r1 * IN_DIM);
    const float4* x2 = (const float4*)(x + (size_t)r2 * IN_DIM);
    const float4* x3 = (const float4*)(x + (size_t)r3 * IN_DIM);
    const float4* w0 = (const float4*)&sWt[(c0 + 0) * IN_DIM];
    const float4* w1 = (const float4*)&sWt[(c0 + 1) * IN_DIM];
    const float4* w2 = (const float4*)&sWt[(c0 + 2) * IN_DIM];
    const float4* w3 = (const float4*)&sWt[(c0 + 3) * IN_DIM];
    float acc[4][4];
#pragma unroll
    for (int r = 0; r < 4; ++r)
#pragma unroll
        for (int cc = 0; cc < 4; ++cc) acc[r][cc] = 0.f;
#pragma unroll 4
    for (int k4 = 0; k4 < IN_DIM / 4; ++k4) {
        float4 v0 = x0[k4], v1 = x1[k4], v2 = x2[k4], v3 = x3[k4];
        int ks = k4 ^ sw;
        float4 wa = w0[ks], wb = w1[ks], wc = w2[ks], wd = w3[ks];
#define DOT4(a, b) (a.x * b.x + a.y * b.y + a.z * b.z + a.w * b.w)
        acc[0][0] += DOT4(v0, wa); acc[0][1] += DOT4(v0, wb);
        acc[0][2] += DOT4(v0, wc); acc[0][3] += DOT4(v0, wd);
        acc[1][0] += DOT4(v1, wa); acc[1][1] += DOT4(v1, wb);
        acc[1][2] += DOT4(v1, wc); acc[1][3] += DOT4(v1, wd);
        acc[2][0] += DOT4(v2, wa); acc[2][1] += DOT4(v2, wb);
        acc[2][2] += DOT4(v2, wc); acc[2][3] += DOT4(v2, wd);
        acc[3][0] += DOT4(v3, wa); acc[3][1] += DOT4(v3, wb);
        acc[3][2] += DOT4(v3, wc); acc[3][3] += DOT4(v3, wd);
#undef DOT4
    }
#pragma unroll
    for (int r = 0; r < 4; ++r) {
        int row = row0 + r;
        if (row < N_NODES) {
            float4 o = make_float4(acc[r][0], acc[r][1], acc[r][2], acc[r][3]);
            *(float4*)&g_h1[(size_t)row * EMB + c0] = o;
        }
    }
}

// layer-1 aggregation FUSED with gemm2: warp per node, float2 per lane.
// Gather loop unrolled 4x int4 (8 edges in flight). Epilogue computes
// h2 = relu(agg+b1) @ W2 in-warp via smem (r1 never materialized).
__global__ void k_agg1(const float* __restrict__ b1, const float* __restrict__ W2) {
    __shared__ float sW2[EMB * NCLS];    // W2[k*18+c]
    __shared__ float sR[8][EMB];         // per-warp r1 row
    int g    = threadIdx.x >> 5;
    int lane = threadIdx.x & 31;
    for (int i = threadIdx.x; i < EMB * NCLS; i += 256) sW2[i] = W2[i];
    __syncthreads();
    int node = blockIdx.x * 8 + g;
    if (node >= N_NODES) return;         // whole warp exits together; after syncthreads
    float dn = g_dis[node];
    float2 h0 = __ldg((const float2*)&g_h1[(size_t)node * EMB] + lane);
    float ax = h0.x * dn * dn, ay = h0.y * dn * dn;   // self loop
    float bx = 0.f, by = 0.f;
    int beg = g_rowp[node];
    int cnt = g_cnt [node];
    int i = 0;
    if ((beg & 1) && cnt > 0) {            // align to int4
        int2 m = __ldg(g_csr + beg);
        float w = __int_as_float(m.y);
        float2 h = __ldg((const float2*)&g_h1[(size_t)m.x * EMB] + lane);
        ax += w * h.x; ay += w * h.y;
        i = 1;
    }
    int rem   = cnt - i;
    int pairs = rem >> 1;
    const int4* p4 = (const int4*)(g_csr + beg + i);
    int j = 0;
    for (; j + 4 <= pairs; j += 4) {       // 8 independent gathers in flight
        int4 ma = __ldg(p4 + j);
        int4 mb = __ldg(p4 + j + 1);
        int4 mc = __ldg(p4 + j + 2);
        int4 md = __ldg(p4 + j + 3);
        float2 ha0 = __ldg((const float2*)&g_h1[(size_t)ma.x * EMB] + lane);
        float2 ha1 = __ldg((const float2*)&g_h1[(size_t)ma.z * EMB] + lane);
        float2 hb0 = __ldg((const float2*)&g_h1[(size_t)mb.x * EMB] + lane);
        float2 hb1 = __ldg((const float2*)&g_h1[(size_t)mb.z * EMB] + lane);
        float2 hc0 = __ldg((const float2*)&g_h1[(size_t)mc.x * EMB] + lane);
        float2 hc1 = __ldg((const float2*)&g_h1[(size_t)mc.z * EMB] + lane);
        float2 hd0 = __ldg((const float2*)&g_h1[(size_t)md.x * EMB] + lane);
        float2 hd1 = __ldg((const float2*)&g_h1[(size_t)md.z * EMB] + lane);
        float wa0 = __int_as_float(ma.y), wa1 = __int_as_float(ma.w);
        float wb0 = __int_as_float(mb.y), wb1 = __int_as_float(mb.w);
        float wc0 = __int_as_float(mc.y), wc1 = __int_as_float(mc.w);
        float wd0 = __int_as_float(md.y), wd1 = __int_as_float(md.w);
        ax += wa0 * ha0.x; ay += wa0 * ha0.y;
        bx += wa1 * ha1.x; by += wa1 * ha1.y;
        ax += wb0 * hb0.x; ay += wb0 * hb0.y;
        bx += wb1 * hb1.x; by += wb1 * hb1.y;
        ax += wc0 * hc0.x; ay += wc0 * hc0.y;
        bx += wc1 * hc1.x; by += wc1 * hc1.y;
        ax += wd0 * hd0.x; ay += wd0 * hd0.y;
        bx += wd1 * hd1.x; by += wd1 * hd1.y;
    }
    for (; j < pairs; ++j) {
        int4 ma = __ldg(p4 + j);
        float wa0 = __int_as_float(ma.y), wa1 = __int_as_float(ma.w);
        float2 ha0 = __ldg((const float2*)&g_h1[(size_t)ma.x * EMB] + lane);
        float2 ha1 = __ldg((const float2*)&g_h1[(size_t)ma.z * EMB] + lane);
        ax += wa0 * ha0.x; ay += wa0 * ha0.y;
        bx += wa1 * ha1.x; by += wa1 * ha1.y;
    }
    if (rem & 1) {                          // tail edge
        int2 m = __ldg(g_csr + beg + cnt - 1);
        float w = __int_as_float(m.y);
        float2 h = __ldg((const float2*)&g_h1[(size_t)m.x * EMB] + lane);
        ax += w * h.x; ay += w * h.y;
    }
    float2 bb = __ldg((const float2*)b1 + lane);
    float rx = fmaxf(ax + bx + bb.x, 0.f);
    float ry = fmaxf(ay + by + bb.y, 0.f);
    // fused gemm2: h2[node] = r1 @ W2
    sR[g][2 * lane]     = rx;
    sR[g][2 * lane + 1] = ry;
    __syncwarp();
    if (lane < NCLS) {
        float acc = 0.f;
#pragma unroll
        for (int k = 0; k < EMB; ++k)
            acc += sR[g][k] * sW2[k * NCLS + lane];   // sR broadcast; sW2 conflict-free
        g_h2[(size_t)node * NCLS + lane] = acc;
    }
}

// layer-2 aggregation fused with +b2 and log_softmax. Warp per node,
// int4 meta (2 edges per warp-uniform LDG).
__global__ void k_agg2_final(const float* __restrict__ b2, float* __restrict__ out,
                             int write_logits) {
    int node = blockIdx.x * 8 + (threadIdx.x >> 5);
    int lane = threadIdx.x & 31;
    if (node >= N_NODES) return;
    bool act = lane < NCLS;
    float dn  = g_dis[node];
    float acc = act ? g_h2[(size_t)node * NCLS + lane] * dn * dn : 0.f;
    float acc2 = 0.f;
    int beg = g_rowp[node];
    int cnt = g_cnt [node];
    int i = 0;
    if ((beg & 1) && cnt > 0) {
        int2 m = __ldg(g_csr + beg);
        if (act) acc += __int_as_float(m.y) * __ldg(&g_h2[(size_t)m.x * NCLS + lane]);
        i = 1;
    }
    int rem   = cnt - i;
    int pairs = rem >> 1;
    const int4* p4 = (const int4*)(g_csr + beg + i);
    for (int j = 0; j < pairs; ++j) {
        int4 ma = __ldg(p4 + j);
        if (act) {
            acc  += __int_as_float(ma.y) * __ldg(&g_h2[(size_t)ma.x * NCLS + lane]);
            acc2 += __int_as_float(ma.w) * __ldg(&g_h2[(size_t)ma.z * NCLS + lane]);
        }
    }
    if (rem & 1) {
        int2 m = __ldg(g_csr + beg + cnt - 1);
        if (act) acc += __int_as_float(m.y) * __ldg(&g_h2[(size_t)m.x * NCLS + lane]);
    }
    float v = acc + acc2 + (act ? b2[lane] : 0.f);
    float mx = act ? v : -1e30f;
#pragma unroll
    for (int off = 16; off >= 1; off >>= 1)
        mx = fmaxf(mx, __shfl_xor_sync(0xffffffffu, mx, off));
    float s = act ? __expf(v - mx) : 0.f;
#pragma unroll
    for (int off = 16; off >= 1; off >>= 1)
        s += __shfl_xor_sync(0xffffffffu, s, off);
    float lse = mx + __logf(s);
    if (act) {
        out[(size_t)node * NCLS + lane] = v - lse;
        if (write_logits)
            out[(size_t)N_NODES * NCLS + (size_t)node * NCLS + lane] = v;
    }
}

// ---------------- launch -----------------------------------------------------
extern "C" void kernel_launch(void* const* d_in, const int* in_sizes, int n_in,
                              void* d_out, int out_size) {
    const float* x  = (const float*)d_in[0];
    const int*   ei = (const int*)d_in[1];     // int64 downcast to int32 by harness
    const float* W1 = (const float*)d_in[2];
    const float* b1 = (const float*)d_in[3];
    const float* W2 = (const float*)d_in[4];
    const float* b2 = (const float*)d_in[5];
    float* out = (float*)d_out;

    int E = in_sizes[1] / 2;
    if (E > MAX_E) E = MAX_E;
    int write_logits = (out_size >= 2 * N_NODES * NCLS) ? 1 : 0;

    // lazy side-stream + events (host-side infra; device work per call unchanged)
    static cudaStream_t s1 = nullptr;
    static cudaEvent_t  ev0 = nullptr, ev1 = nullptr;
    static int init_done = 0;
    if (!init_done) {
        init_done = 1;
        if (cudaStreamCreateWithFlags(&s1, cudaStreamNonBlocking) != cudaSuccess) s1 = nullptr;
        if (s1) {
            if (cudaEventCreateWithFlags(&ev0, cudaEventDisableTiming) != cudaSuccess ||
                cudaEventCreateWithFlags(&ev1, cudaEventDisableTiming) != cudaSuccess) {
                s1 = nullptr;
            }
        }
    }

    void* cnt_ptr = nullptr;
    cudaGetSymbolAddress(&cnt_ptr, g_cnt);
    cudaMemsetAsync(cnt_ptr, 0, N_NODES * sizeof(int));

    int nE4 = (E + 1023) / 1024;  // 4 edges per thread, 256 threads/block

    if (s1) {
        // fork: gemm1 (independent) runs parallel to the CSR build chain
        cudaEventRecord(ev0, 0);
        cudaStreamWaitEvent(s1, ev0, 0);
        k_gemm1<<<(N_NODES + G1_TILE - 1) / G1_TILE, 256, 0, s1>>>(x, W1);
        cudaEventRecord(ev1, s1);

        k_deg  <<<nE4, 256>>>(ei, E);
        k_scanA<<<NBLK, NCHUNK>>>();
        k_scanC<<<NBLK, NCHUNK>>>();
        k_fill <<<(E + 255) / 256, 256>>>(ei, E);

        cudaStreamWaitEvent(0, ev1, 0);    // join before agg1
    } else {
        k_deg  <<<nE4, 256>>>(ei, E);
        k_scanA<<<NBLK, NCHUNK>>>();
        k_scanC<<<NBLK, NCHUNK>>>();
        k_fill <<<(E + 255) / 256, 256>>>(ei, E);
        k_gemm1<<<(N_NODES + G1_TILE - 1) / G1_TILE, 256>>>(x, W1);
    }

    k_agg1 <<<(N_NODES + 7) / 8, 256>>>(b1, W2);
    k_agg2_final<<<(N_NODES + 7) / 8, 256>>>(b2, out, write_logits);
}

// round 17
// speedup vs baseline: 3.7976x; 1.0370x over previous
#include <cuda_runtime.h>
#include <cuda_fp16.h>
#include <cstdint>

#define N_NODES 100000
#define IN_DIM  128
#define EMB     64
#define NCLS    18
#define MAX_E   3200000
#define NCHUNK  512
#define NBLK    ((N_NODES + NCHUNK - 1) / NCHUNK)   // 196

// ---------------- scratch (static device globals; no allocs) ----------------
__device__ int    g_cnt [N_NODES];     // in-degree (excl self loop)
__device__ int    g_rowp[N_NODES];     // CSR row start
__device__ int    g_cur [N_NODES];     // fill cursor
__device__ float  g_dis [N_NODES];     // rsqrt(deg incl self loop)
__device__ int    g_part[NBLK];        // per-chunk partial sums
__device__ __half g_h1  [N_NODES * EMB];   // fp16 h1 (halves gather traffic)
__device__ float  g_h2  [N_NODES * NCLS];
__device__ int4   g_csr4[MAX_E / 2 + 1];   // 16B-aligned backing for CSR
#define g_csr ((int2*)g_csr4)              // (src, bitcast norm), dst-sorted

// ---------------- kernels ---------------------------------------------------

// in-degree count; int4 loads = 4 edges per LDG
__global__ void k_deg(const int* __restrict__ ei, int E) {
    int t = blockIdx.x * blockDim.x + threadIdx.x;
    int e4 = t * 4;
    if (e4 + 4 <= E) {
        int4 d = __ldg((const int4*)(ei + E) + t);
        if ((unsigned)d.x < N_NODES) atomicAdd(&g_cnt[d.x], 1);
        if ((unsigned)d.y < N_NODES) atomicAdd(&g_cnt[d.y], 1);
        if ((unsigned)d.z < N_NODES) atomicAdd(&g_cnt[d.z], 1);
        if ((unsigned)d.w < N_NODES) atomicAdd(&g_cnt[d.w], 1);
    } else {
        for (int e = e4; e < E; ++e) {
            int d = __ldg(ei + E + e);
            if ((unsigned)d < N_NODES) atomicAdd(&g_cnt[d], 1);
        }
    }
}

// parallel scan stage A: coalesced per-chunk partial sums
__global__ void k_scanA() {
    __shared__ int sred[NCHUNK];
    int b = blockIdx.x;
    int i = b * NCHUNK + threadIdx.x;
    sred[threadIdx.x] = (i < N_NODES) ? g_cnt[i] : 0;
    __syncthreads();
    for (int off = NCHUNK / 2; off >= 1; off >>= 1) {
        if (threadIdx.x < off) sred[threadIdx.x] += sred[threadIdx.x + off];
        __syncthreads();
    }
    if (threadIdx.x == 0) g_part[b] = sred[0];
}

// parallel scan stage C: per-chunk inclusive scan + cross-chunk offset
__global__ void k_scanC() {
    __shared__ int s[NCHUNK];
    __shared__ int soff;
    int b = blockIdx.x;
    int t = threadIdx.x;
    int i = b * NCHUNK + t;
    int v = (i < N_NODES) ? g_cnt[i] : 0;
    s[t] = v;
    __syncthreads();
    for (int off = 1; off < NCHUNK; off <<= 1) {
        int u = (t >= off) ? s[t - off] : 0;
        __syncthreads();
        s[t] += u;
        __syncthreads();
    }
    if (t < 32) {
        int acc = 0;
        for (int j = t; j < b; j += 32) acc += g_part[j];
#pragma unroll
        for (int o = 16; o >= 1; o >>= 1) acc += __shfl_xor_sync(0xffffffffu, acc, o);
        if (t == 0) soff = acc;
    }
    __syncthreads();
    if (i < N_NODES) {
        int excl = s[t] + soff - v;
        g_rowp[i] = excl;
        g_cur [i] = excl;
        g_dis [i] = rsqrtf((float)(v + 1));
    }
}

// scatter (src, norm) into dst-sorted CSR slots; 4 edges per thread
__global__ void k_fill(const int* __restrict__ ei, int E) {
    int t = blockIdx.x * blockDim.x + threadIdx.x;
    int e4 = t * 4;
    if (e4 + 4 <= E) {
        int4 s = __ldg((const int4*)ei + t);
        int4 d = __ldg((const int4*)(ei + E) + t);
        if ((unsigned)s.x >= N_NODES) s.x = 0;
        if ((unsigned)s.y >= N_NODES) s.y = 0;
        if ((unsigned)s.z >= N_NODES) s.z = 0;
        if ((unsigned)s.w >= N_NODES) s.w = 0;
        if ((unsigned)d.x >= N_NODES) d.x = 0;
        if ((unsigned)d.y >= N_NODES) d.y = 0;
        if ((unsigned)d.z >= N_NODES) d.z = 0;
        if ((unsigned)d.w >= N_NODES) d.w = 0;
        float n0 = g_dis[s.x] * g_dis[d.x];
        float n1 = g_dis[s.y] * g_dis[d.y];
        float n2 = g_dis[s.z] * g_dis[d.z];
        float n3 = g_dis[s.w] * g_dis[d.w];
        g_csr[atomicAdd(&g_cur[d.x], 1)] = make_int2(s.x, __float_as_int(n0));
        g_csr[atomicAdd(&g_cur[d.y], 1)] = make_int2(s.y, __float_as_int(n1));
        g_csr[atomicAdd(&g_cur[d.z], 1)] = make_int2(s.z, __float_as_int(n2));
        g_csr[atomicAdd(&g_cur[d.w], 1)] = make_int2(s.w, __float_as_int(n3));
    } else {
        for (int e = e4; e < E; ++e) {
            int s = __ldg(ei + e);
            int d = __ldg(ei + E + e);
            if ((unsigned)s >= N_NODES) s = 0;
            if ((unsigned)d >= N_NODES) d = 0;
            float nrm = g_dis[s] * g_dis[d];
            g_csr[atomicAdd(&g_cur[d], 1)] = make_int2(s, __float_as_int(nrm));
        }
    }
}

// h1 = x @ W1  (100000x128 @ 128x64). 4x4 register blocking (validated R11).
// Output stored fp16 (2x half2 per row-chunk).
#define G1_TILE 64
__global__ void k_gemm1(const float* __restrict__ x, const float* __restrict__ W1) {
    __shared__ float sWt[EMB * IN_DIM];  // 32 KB, swizzled float4 layout
    for (int i = threadIdx.x; i < IN_DIM * EMB; i += blockDim.x) {
        int k = i >> 6, c = i & 63;      // W1 is [128,64] row-major
        int k4 = k >> 2, j = k & 3;
        int cg = c >> 2;
        sWt[(c * 32 + (k4 ^ (cg & 7))) * 4 + j] = W1[i];
    }
    __syncthreads();
    int rowgrp = threadIdx.x >> 4;        // 0..15
    int colgrp = threadIdx.x & 15;        // 0..15
    int sw     = colgrp & 7;
    int c0     = colgrp * 4;
    int row0   = blockIdx.x * G1_TILE + rowgrp * 4;
    int r0 = min(row0 + 0, N_NODES - 1);
    int r1 = min(row0 + 1, N_NODES - 1);
    int r2 = min(row0 + 2, N_NODES - 1);
    int r3 = min(row0 + 3, N_NODES - 1);
    const float4* x0 = (const float4*)(x + (size_t)r0 * IN_DIM);
    const float4* x1 = (const float4*)(x + (size_t)r1 * IN_DIM);
    const float4* x2 = (const float4*)(x + (size_t)r2 * IN_DIM);
    const float4* x3 = (const float4*)(x + (size_t)r3 * IN_DIM);
    const float4* w0 = (const float4*)&sWt[(c0 + 0) * IN_DIM];
    const float4* w1 = (const float4*)&sWt[(c0 + 1) * IN_DIM];
    const float4* w2 = (const float4*)&sWt[(c0 + 2) * IN_DIM];
    const float4* w3 = (const float4*)&sWt[(c0 + 3) * IN_DIM];
    float acc[4][4];
#pragma unroll
    for (int r = 0; r < 4; ++r)
#pragma unroll
        for (int cc = 0; cc < 4; ++cc) acc[r][cc] = 0.f;
#pragma unroll 4
    for (int k4 = 0; k4 < IN_DIM / 4; ++k4) {
        float4 v0 = x0[k4], v1 = x1[k4], v2 = x2[k4], v3 = x3[k4];
        int ks = k4 ^ sw;
        float4 wa = w0[ks], wb = w1[ks], wc = w2[ks], wd = w3[ks];
#define DOT4(a, b) (a.x * b.x + a.y * b.y + a.z * b.z + a.w * b.w)
        acc[0][0] += DOT4(v0, wa); acc[0][1] += DOT4(v0, wb);
        acc[0][2] += DOT4(v0, wc); acc[0][3] += DOT4(v0, wd);
        acc[1][0] += DOT4(v1, wa); acc[1][1] += DOT4(v1, wb);
        acc[1][2] += DOT4(v1, wc); acc[1][3] += DOT4(v1, wd);
        acc[2][0] += DOT4(v2, wa); acc[2][1] += DOT4(v2, wb);
        acc[2][2] += DOT4(v2, wc); acc[2][3] += DOT4(v2, wd);
        acc[3][0] += DOT4(v3, wa); acc[3][1] += DOT4(v3, wb);
        acc[3][2] += DOT4(v3, wc); acc[3][3] += DOT4(v3, wd);
#undef DOT4
    }
#pragma unroll
    for (int r = 0; r < 4; ++r) {
        int row = row0 + r;
        if (row < N_NODES) {
            __half2 p0 = __floats2half2_rn(acc[r][0], acc[r][1]);
            __half2 p1 = __floats2half2_rn(acc[r][2], acc[r][3]);
            __half2* dst = (__half2*)&g_h1[(size_t)row * EMB + c0];
            dst[0] = p0;
            dst[1] = p1;
        }
    }
}

// layer-1 aggregation FUSED with gemm2: warp per node, half2 (2 cols) per lane
// -> each gather touches ONE 128B line. Unrolled 4x int4 (8 edges in flight).
// Accumulation fp32. Epilogue computes h2 = relu(agg+b1) @ W2 in-warp.
__global__ void k_agg1(const float* __restrict__ b1, const float* __restrict__ W2) {
    __shared__ float sW2[EMB * NCLS];    // W2[k*18+c]
    __shared__ float sR[8][EMB];         // per-warp r1 row
    int g    = threadIdx.x >> 5;
    int lane = threadIdx.x & 31;
    for (int i = threadIdx.x; i < EMB * NCLS; i += 256) sW2[i] = W2[i];
    __syncthreads();
    int node = blockIdx.x * 8 + g;
    if (node >= N_NODES) return;         // warp-uniform exit; after syncthreads
    float dn = g_dis[node];
    float2 h0 = __half22float2(__ldg((const __half2*)&g_h1[(size_t)node * EMB] + lane));
    float ax = h0.x * dn * dn, ay = h0.y * dn * dn;   // self loop
    float bx = 0.f, by = 0.f;
    int beg = g_rowp[node];
    int cnt = g_cnt [node];
    int i = 0;
    if ((beg & 1) && cnt > 0) {            // align to int4
        int2 m = __ldg(g_csr + beg);
        float w = __int_as_float(m.y);
        float2 h = __half22float2(__ldg((const __half2*)&g_h1[(size_t)m.x * EMB] + lane));
        ax += w * h.x; ay += w * h.y;
        i = 1;
    }
    int rem   = cnt - i;
    int pairs = rem >> 1;
    const int4* p4 = (const int4*)(g_csr + beg + i);
    int j = 0;
    for (; j + 4 <= pairs; j += 4) {       // 8 independent gathers in flight
        int4 ma = __ldg(p4 + j);
        int4 mb = __ldg(p4 + j + 1);
        int4 mc = __ldg(p4 + j + 2);
        int4 md = __ldg(p4 + j + 3);
        __half2 qa0 = __ldg((const __half2*)&g_h1[(size_t)ma.x * EMB] + lane);
        __half2 qa1 = __ldg((const __half2*)&g_h1[(size_t)ma.z * EMB] + lane);
        __half2 qb0 = __ldg((const __half2*)&g_h1[(size_t)mb.x * EMB] + lane);
        __half2 qb1 = __ldg((const __half2*)&g_h1[(size_t)mb.z * EMB] + lane);
        __half2 qc0 = __ldg((const __half2*)&g_h1[(size_t)mc.x * EMB] + lane);
        __half2 qc1 = __ldg((const __half2*)&g_h1[(size_t)mc.z * EMB] + lane);
        __half2 qd0 = __ldg((const __half2*)&g_h1[(size_t)md.x * EMB] + lane);
        __half2 qd1 = __ldg((const __half2*)&g_h1[(size_t)md.z * EMB] + lane);
        float2 ha0 = __half22float2(qa0), ha1 = __half22float2(qa1);
        float2 hb0 = __half22float2(qb0), hb1 = __half22float2(qb1);
        float2 hc0 = __half22float2(qc0), hc1 = __half22float2(qc1);
        float2 hd0 = __half22float2(qd0), hd1 = __half22float2(qd1);
        float wa0 = __int_as_float(ma.y), wa1 = __int_as_float(ma.w);
        float wb0 = __int_as_float(mb.y), wb1 = __int_as_float(mb.w);
        float wc0 = __int_as_float(mc.y), wc1 = __int_as_float(mc.w);
        float wd0 = __int_as_float(md.y), wd1 = __int_as_float(md.w);
        ax += wa0 * ha0.x; ay += wa0 * ha0.y;
        bx += wa1 * ha1.x; by += wa1 * ha1.y;
        ax += wb0 * hb0.x; ay += wb0 * hb0.y;
        bx += wb1 * hb1.x; by += wb1 * hb1.y;
        ax += wc0 * hc0.x; ay += wc0 * hc0.y;
        bx += wc1 * hc1.x; by += wc1 * hc1.y;
        ax += wd0 * hd0.x; ay += wd0 * hd0.y;
        bx += wd1 * hd1.x; by += wd1 * hd1.y;
    }
    for (; j < pairs; ++j) {
        int4 ma = __ldg(p4 + j);
        float wa0 = __int_as_float(ma.y), wa1 = __int_as_float(ma.w);
        float2 ha0 = __half22float2(__ldg((const __half2*)&g_h1[(size_t)ma.x * EMB] + lane));
        float2 ha1 = __half22float2(__ldg((const __half2*)&g_h1[(size_t)ma.z * EMB] + lane));
        ax += wa0 * ha0.x; ay += wa0 * ha0.y;
        bx += wa1 * ha1.x; by += wa1 * ha1.y;
    }
    if (rem & 1) {                          // tail edge
        int2 m = __ldg(g_csr + beg + cnt - 1);
        float w = __int_as_float(m.y);
        float2 h = __half22float2(__ldg((const __half2*)&g_h1[(size_t)m.x * EMB] + lane));
        ax += w * h.x; ay += w * h.y;
    }
    float2 bb = __ldg((const float2*)b1 + lane);
    float rx = fmaxf(ax + bx + bb.x, 0.f);
    float ry = fmaxf(ay + by + bb.y, 0.f);
    // fused gemm2: h2[node] = r1 @ W2
    sR[g][2 * lane]     = rx;
    sR[g][2 * lane + 1] = ry;
    __syncwarp();
    if (lane < NCLS) {
        float acc = 0.f;
#pragma unroll
        for (int k = 0; k < EMB; ++k)
            acc += sR[g][k] * sW2[k * NCLS + lane];   // sR broadcast; sW2 conflict-free
        g_h2[(size_t)node * NCLS + lane] = acc;
    }
}

// layer-2 aggregation fused with +b2 and log_softmax. Warp per node,
// int4 meta (2 edges per warp-uniform LDG).
__global__ void k_agg2_final(const float* __restrict__ b2, float* __restrict__ out,
                             int write_logits) {
    int node = blockIdx.x * 8 + (threadIdx.x >> 5);
    int lane = threadIdx.x & 31;
    if (node >= N_NODES) return;
    bool act = lane < NCLS;
    float dn  = g_dis[node];
    float acc = act ? g_h2[(size_t)node * NCLS + lane] * dn * dn : 0.f;
    float acc2 = 0.f;
    int beg = g_rowp[node];
    int cnt = g_cnt [node];
    int i = 0;
    if ((beg & 1) && cnt > 0) {
        int2 m = __ldg(g_csr + beg);
        if (act) acc += __int_as_float(m.y) * __ldg(&g_h2[(size_t)m.x * NCLS + lane]);
        i = 1;
    }
    int rem   = cnt - i;
    int pairs = rem >> 1;
    const int4* p4 = (const int4*)(g_csr + beg + i);
    for (int j = 0; j < pairs; ++j) {
        int4 ma = __ldg(p4 + j);
        if (act) {
            acc  += __int_as_float(ma.y) * __ldg(&g_h2[(size_t)ma.x * NCLS + lane]);
            acc2 += __int_as_float(ma.w) * __ldg(&g_h2[(size_t)ma.z * NCLS + lane]);
        }
    }
    if (rem & 1) {
        int2 m = __ldg(g_csr + beg + cnt - 1);
        if (act) acc += __int_as_float(m.y) * __ldg(&g_h2[(size_t)m.x * NCLS + lane]);
    }
    float v = acc + acc2 + (act ? b2[lane] : 0.f);
    float mx = act ? v : -1e30f;
#pragma unroll
    for (int off = 16; off >= 1; off >>= 1)
        mx = fmaxf(mx, __shfl_xor_sync(0xffffffffu, mx, off));
    float s = act ? __expf(v - mx) : 0.f;
#pragma unroll
    for (int off = 16; off >= 1; off >>= 1)
        s += __shfl_xor_sync(0xffffffffu, s, off);
    float lse = mx + __logf(s);
    if (act) {
        out[(size_t)node * NCLS + lane] = v - lse;
        if (write_logits)
            out[(size_t)N_NODES * NCLS + (size_t)node * NCLS + lane] = v;
    }
}

// ---------------- launch -----------------------------------------------------
extern "C" void kernel_launch(void* const* d_in, const int* in_sizes, int n_in,
                              void* d_out, int out_size) {
    const float* x  = (const float*)d_in[0];
    const int*   ei = (const int*)d_in[1];     // int64 downcast to int32 by harness
    const float* W1 = (const float*)d_in[2];
    const float* b1 = (const float*)d_in[3];
    const float* W2 = (const float*)d_in[4];
    const float* b2 = (const float*)d_in[5];
    float* out = (float*)d_out;

    int E = in_sizes[1] / 2;
    if (E > MAX_E) E = MAX_E;
    int write_logits = (out_size >= 2 * N_NODES * NCLS) ? 1 : 0;

    // lazy side-stream + events (host-side infra; device work per call unchanged)
    static cudaStream_t s1 = nullptr;
    static cudaEvent_t  ev0 = nullptr, ev1 = nullptr;
    static int init_done = 0;
    if (!init_done) {
        init_done = 1;
        if (cudaStreamCreateWithFlags(&s1, cudaStreamNonBlocking) != cudaSuccess) s1 = nullptr;
        if (s1) {
            if (cudaEventCreateWithFlags(&ev0, cudaEventDisableTiming) != cudaSuccess ||
                cudaEventCreateWithFlags(&ev1, cudaEventDisableTiming) != cudaSuccess) {
                s1 = nullptr;
            }
        }
    }

    void* cnt_ptr = nullptr;
    cudaGetSymbolAddress(&cnt_ptr, g_cnt);
    cudaMemsetAsync(cnt_ptr, 0, N_NODES * sizeof(int));

    int nE4 = (E + 1023) / 1024;  // 4 edges per thread, 256 threads/block

    if (s1) {
        // fork: gemm1 (independent) runs parallel to the CSR build chain
        cudaEventRecord(ev0, 0);
        cudaStreamWaitEvent(s1, ev0, 0);
        k_gemm1<<<(N_NODES + G1_TILE - 1) / G1_TILE, 256, 0, s1>>>(x, W1);
        cudaEventRecord(ev1, s1);

        k_deg  <<<nE4, 256>>>(ei, E);
        k_scanA<<<NBLK, NCHUNK>>>();
        k_scanC<<<NBLK, NCHUNK>>>();
        k_fill <<<nE4, 256>>>(ei, E);

        cudaStreamWaitEvent(0, ev1, 0);    // join before agg1
    } else {
        k_deg  <<<nE4, 256>>>(ei, E);
        k_scanA<<<NBLK, NCHUNK>>>();
        k_scanC<<<NBLK, NCHUNK>>>();
        k_fill <<<nE4, 256>>>(ei, E);
        k_gemm1<<<(N_NODES + G1_TILE - 1) / G1_TILE, 256>>>(x, W1);
    }

    k_agg1 <<<(N_NODES + 7) / 8, 256>>>(b1, W2);
    k_agg2_final<<<(N_NODES + 7) / 8, 256>>>(b2, out, write_logits);
}